// round 4
// baseline (speedup 1.0000x reference)
#include <cuda_runtime.h>
#include <cstdint>

#define NN 100000
#define EE 1600000
#define SCAN_B 1024
#define NBLK ((NN + SCAN_B - 1) / SCAN_B)   // 98

// ---------------- scratch (static device arrays; no allocation) ----------------
__device__ float g_deg[NN];
__device__ float g_dinv[NN];
__device__ int   g_cnt[NN];
__device__ int   g_rowptr[NN + 1];
__device__ int   g_fill[NN];
__device__ int   g_blksum[NBLK];
__device__ int   g_blkoff[NBLK + 1];
__device__ int   g_src_s[EE];    // edge sources in CSR(dst) order
__device__ float g_norm_s[EE];   // dinv[src]*w in CSR(dst) order
__device__ float g_h1[(size_t)NN * 128];
__device__ float g_a1[(size_t)NN * 128];
__device__ float g_h2[(size_t)NN * 64];
__device__ float g_W1hi[128 * 128];
__device__ float g_W1lo[128 * 128];
__device__ float g_W2hi[128 * 64];
__device__ float g_W2lo[128 * 64];

// ---------------- tf32 split helpers ----------------
__device__ __forceinline__ void split_tf32(float x, float& hi, float& lo) {
    uint32_t h;
    asm("cvt.rna.tf32.f32 %0, %1;" : "=r"(h) : "f"(x));
    hi = __uint_as_float(h);
    float r = x - hi;                    // exact in fp32
    uint32_t l;
    asm("cvt.rna.tf32.f32 %0, %1;" : "=r"(l) : "f"(r));
    lo = __uint_as_float(l);
}

#define MMA_TF32(c, a, b0, b1)                                            \
    asm volatile("mma.sync.aligned.m16n8k8.row.col.f32.tf32.tf32.f32 "    \
        "{%0,%1,%2,%3}, {%4,%5,%6,%7}, {%8,%9}, {%0,%1,%2,%3};"           \
        : "+f"(c[0]), "+f"(c[1]), "+f"(c[2]), "+f"(c[3])                  \
        : "r"(a[0]), "r"(a[1]), "r"(a[2]), "r"(a[3]), "r"(b0), "r"(b1))

// ---------------- degree + histogram ----------------
__global__ void zero_kernel(int n) {
    int i = blockIdx.x * blockDim.x + threadIdx.x;
    if (i < n) { g_deg[i] = 0.0f; g_cnt[i] = 0; }
}

__global__ void deg_hist_kernel(const int* __restrict__ dst,
                                const float* __restrict__ w, int E) {
    int e = blockIdx.x * blockDim.x + threadIdx.x;
    if (e < E) {
        int d = dst[e];
        atomicAdd(&g_deg[d], w[e]);
        atomicAdd(&g_cnt[d], 1);
    }
}

__global__ void dinv_kernel(int n) {
    int i = blockIdx.x * blockDim.x + threadIdx.x;
    if (i < n) g_dinv[i] = rsqrtf(g_deg[i] + 1.0f);  // +1 = self loop weight
}

// ---------------- W split kernel ----------------
__global__ void convw_kernel(const float* __restrict__ W,
                             float* __restrict__ hi,
                             float* __restrict__ lo, int sz) {
    int i = blockIdx.x * blockDim.x + threadIdx.x;
    if (i < sz) {
        float h, l;
        split_tf32(W[i], h, l);
        hi[i] = h; lo[i] = l;
    }
}

// ---------------- hierarchical scan: local pass ----------------
__global__ void scan_local_kernel(int n) {
    __shared__ int warp_sums[32];
    int tid  = threadIdx.x;
    int i    = blockIdx.x * SCAN_B + tid;
    int lane = tid & 31;
    int wid  = tid >> 5;

    int v = (i < n) ? g_cnt[i] : 0;

    int s = v;
    #pragma unroll
    for (int off = 1; off < 32; off <<= 1) {
        int t = __shfl_up_sync(0xffffffffu, s, off);
        if (lane >= off) s += t;
    }
    if (lane == 31) warp_sums[wid] = s;
    __syncthreads();

    if (wid == 0) {
        int ws = warp_sums[lane];
        int sw = ws;
        #pragma unroll
        for (int off = 1; off < 32; off <<= 1) {
            int t = __shfl_up_sync(0xffffffffu, sw, off);
            if (lane >= off) sw += t;
        }
        warp_sums[lane] = sw - ws;  // exclusive
        if (lane == 31 && blockIdx.x < NBLK) g_blksum[blockIdx.x] = sw;
    }
    __syncthreads();

    int excl = s - v + warp_sums[wid];
    if (i < n) g_rowptr[i] = excl;
}

__global__ void scan_blocks_kernel(int n) {
    __shared__ int sh[128];
    int tid = threadIdx.x;  // 128 threads
    int v = (tid < NBLK) ? g_blksum[tid] : 0;
    sh[tid] = v;
    __syncthreads();
    #pragma unroll
    for (int off = 1; off < 128; off <<= 1) {
        int t = (tid >= off) ? sh[tid - off] : 0;
        __syncthreads();
        sh[tid] += t;
        __syncthreads();
    }
    if (tid < NBLK) g_blkoff[tid] = sh[tid] - v;
    if (tid == 127) g_rowptr[n] = sh[127];
}

__global__ void scan_apply_kernel(int n) {
    int i = blockIdx.x * blockDim.x + threadIdx.x;
    if (i < n) {
        int r = g_rowptr[i] + g_blkoff[i >> 10];
        g_rowptr[i] = r;
        g_fill[i]   = r;
    }
}

// ---------------- scatter edges into CSR order ----------------
__global__ void scatter_kernel(const int* __restrict__ src,
                               const int* __restrict__ dst,
                               const float* __restrict__ w, int E) {
    int e = blockIdx.x * blockDim.x + threadIdx.x;
    if (e < E) {
        int d = dst[e];
        int s = src[e];
        int pos = atomicAdd(&g_fill[d], 1);
        g_src_s[pos]  = s;
        g_norm_s[pos] = g_dinv[s] * w[e];
    }
}

// ---------------- tensor-core GEMM: C[n,OUTD] = A[n,128] @ W[128,OUTD] -------
// 3xTF32: W pre-split into hi/lo globals; A split on the fly in smem load.
template <int OUTD, int WARPS_M, int WARPS_N>
__global__ void __launch_bounds__(256)
gemm_tc_kernel(const float* __restrict__ A,
               const float* __restrict__ Whi,
               const float* __restrict__ Wlo,
               float* __restrict__ C, int n) {
    constexpr int KC = 16;
    constexpr int MT = 128 / (WARPS_M * 16);   // m16 tiles per warp
    constexpr int NT = OUTD / (WARPS_N * 8);   // n8 tiles per warp
    __shared__ float As_hi[128][KC + 1];
    __shared__ float As_lo[128][KC + 1];
    __shared__ float Bs_hi[KC][OUTD + 4];
    __shared__ float Bs_lo[KC][OUTD + 4];

    int tid  = threadIdx.x;
    int wid  = tid >> 5, lane = tid & 31;
    int wm   = wid / WARPS_N, wn = wid % WARPS_N;
    int g    = lane >> 2, tg = lane & 3;
    int row0 = blockIdx.x * 128;

    float acc[MT][NT][4];
    #pragma unroll
    for (int mi = 0; mi < MT; mi++)
        #pragma unroll
        for (int ni = 0; ni < NT; ni++)
            #pragma unroll
            for (int q = 0; q < 4; q++) acc[mi][ni][q] = 0.f;

    for (int kc = 0; kc < 128; kc += KC) {
        // load + split A chunk: 128 rows x 16 k
        {
            int r  = tid >> 2;   // 0..63
            int c4 = tid & 3;    // 0..3
            #pragma unroll
            for (int h = 0; h < 2; h++) {
                int row  = r + h * 64;
                int grow = row0 + row;
                float4 v = (grow < n)
                    ? *(const float4*)&A[(size_t)grow * 128 + kc + c4 * 4]
                    : make_float4(0.f, 0.f, 0.f, 0.f);
                float hx, lx;
                split_tf32(v.x, hx, lx); As_hi[row][c4*4+0] = hx; As_lo[row][c4*4+0] = lx;
                split_tf32(v.y, hx, lx); As_hi[row][c4*4+1] = hx; As_lo[row][c4*4+1] = lx;
                split_tf32(v.z, hx, lx); As_hi[row][c4*4+2] = hx; As_lo[row][c4*4+2] = lx;
                split_tf32(v.w, hx, lx); As_hi[row][c4*4+3] = hx; As_lo[row][c4*4+3] = lx;
            }
        }
        // load W chunk (pre-split): KC x OUTD
        {
            constexpr int TOT4 = KC * OUTD / 4;
            #pragma unroll
            for (int i = tid; i < TOT4; i += 256) {
                int kk = i / (OUTD / 4), c4 = i % (OUTD / 4);
                *(float4*)&Bs_hi[kk][c4*4] =
                    *(const float4*)&Whi[(size_t)(kc + kk) * OUTD + c4 * 4];
                *(float4*)&Bs_lo[kk][c4*4] =
                    *(const float4*)&Wlo[(size_t)(kc + kk) * OUTD + c4 * 4];
            }
        }
        __syncthreads();
        #pragma unroll
        for (int ks = 0; ks < KC; ks += 8) {
            uint32_t ah[MT][4], al[MT][4];
            #pragma unroll
            for (int mi = 0; mi < MT; mi++) {
                int br = wm * MT * 16 + mi * 16;
                ah[mi][0] = __float_as_uint(As_hi[br + g    ][ks + tg    ]);
                ah[mi][1] = __float_as_uint(As_hi[br + g + 8][ks + tg    ]);
                ah[mi][2] = __float_as_uint(As_hi[br + g    ][ks + tg + 4]);
                ah[mi][3] = __float_as_uint(As_hi[br + g + 8][ks + tg + 4]);
                al[mi][0] = __float_as_uint(As_lo[br + g    ][ks + tg    ]);
                al[mi][1] = __float_as_uint(As_lo[br + g + 8][ks + tg    ]);
                al[mi][2] = __float_as_uint(As_lo[br + g    ][ks + tg + 4]);
                al[mi][3] = __float_as_uint(As_lo[br + g + 8][ks + tg + 4]);
            }
            #pragma unroll
            for (int ni = 0; ni < NT; ni++) {
                int bc = wn * NT * 8 + ni * 8 + g;
                uint32_t bh0 = __float_as_uint(Bs_hi[ks + tg    ][bc]);
                uint32_t bh1 = __float_as_uint(Bs_hi[ks + tg + 4][bc]);
                uint32_t bl0 = __float_as_uint(Bs_lo[ks + tg    ][bc]);
                uint32_t bl1 = __float_as_uint(Bs_lo[ks + tg + 4][bc]);
                #pragma unroll
                for (int mi = 0; mi < MT; mi++) {
                    MMA_TF32(acc[mi][ni], ah[mi], bh0, bh1);
                    MMA_TF32(acc[mi][ni], ah[mi], bl0, bl1);
                    MMA_TF32(acc[mi][ni], al[mi], bh0, bh1);
                }
            }
        }
        __syncthreads();
    }
    // epilogue
    #pragma unroll
    for (int mi = 0; mi < MT; mi++) {
        #pragma unroll
        for (int ni = 0; ni < NT; ni++) {
            int row = row0 + wm * MT * 16 + mi * 16 + g;
            int col = wn * NT * 8 + ni * 8 + tg * 2;
            if (row < n) {
                float2 v0 = make_float2(acc[mi][ni][0], acc[mi][ni][1]);
                *(float2*)&C[(size_t)row * OUTD + col] = v0;
            }
            if (row + 8 < n) {
                float2 v1 = make_float2(acc[mi][ni][2], acc[mi][ni][3]);
                *(float2*)&C[(size_t)(row + 8) * OUTD + col] = v1;
            }
        }
    }
}

// ---------------- CSR aggregation: one warp per node, no atomics -------------
template <int D, bool RELU>
__device__ __forceinline__ void agg_body(const float* __restrict__ h,
                                         const float* __restrict__ bias,
                                         float* __restrict__ out, int n) {
    constexpr int V = D / 32;       // 4 (D=128) or 2 (D=64)
    int gwarp = (blockIdx.x * blockDim.x + threadIdx.x) >> 5;
    int lane  = threadIdx.x & 31;
    if (gwarp >= n) return;
    int node = gwarp;

    float dv = g_dinv[node];
    float acc[V];
    #pragma unroll
    for (int i = 0; i < V; i++) acc[i] = 0.f;

    int beg = g_rowptr[node];
    int end = g_rowptr[node + 1];
    for (int e = beg; e < end; e++) {
        int   s  = g_src_s[e];
        float nm = g_norm_s[e] * dv;
        const float* hp = &h[(size_t)s * D + lane * V];
        if (V == 4) {
            float4 v = *(const float4*)hp;
            acc[0] += nm * v.x; acc[1] += nm * v.y;
            acc[2] += nm * v.z; acc[3] += nm * v.w;
        } else {
            float2 v = *(const float2*)hp;
            acc[0] += nm * v.x; acc[1] += nm * v.y;
        }
    }
    // self loop: norm = dinv[n]^2
    {
        float nm = dv * dv;
        const float* hp = &h[(size_t)node * D + lane * V];
        if (V == 4) {
            float4 v = *(const float4*)hp;
            acc[0] += nm * v.x; acc[1] += nm * v.y;
            acc[2] += nm * v.z; acc[3] += nm * v.w;
        } else {
            float2 v = *(const float2*)hp;
            acc[0] += nm * v.x; acc[1] += nm * v.y;
        }
    }
    float* op = &out[(size_t)node * D + lane * V];
    if (V == 4) {
        float4 r;
        r.x = acc[0] + bias[lane * 4 + 0];
        r.y = acc[1] + bias[lane * 4 + 1];
        r.z = acc[2] + bias[lane * 4 + 2];
        r.w = acc[3] + bias[lane * 4 + 3];
        if (RELU) {
            r.x = fmaxf(r.x, 0.f); r.y = fmaxf(r.y, 0.f);
            r.z = fmaxf(r.z, 0.f); r.w = fmaxf(r.w, 0.f);
        }
        *(float4*)op = r;
    } else {
        float2 r;
        r.x = acc[0] + bias[lane * 2 + 0];
        r.y = acc[1] + bias[lane * 2 + 1];
        if (RELU) { r.x = fmaxf(r.x, 0.f); r.y = fmaxf(r.y, 0.f); }
        *(float2*)op = r;
    }
}

__global__ void agg1_kernel(const float* __restrict__ b1, int n) {
    agg_body<128, true>(g_h1, b1, g_a1, n);
}
__global__ void agg2_kernel(const float* __restrict__ b2,
                            float* __restrict__ out, int n) {
    agg_body<64, false>(g_h2, b2, out, n);
}

// ---------------- launch ----------------
extern "C" void kernel_launch(void* const* d_in, const int* in_sizes, int n_in,
                              void* d_out, int out_size) {
    const float* x  = (const float*)d_in[0];
    const int*   ei = (const int*)  d_in[1];
    const float* w  = (const float*)d_in[2];
    const float* W1 = (const float*)d_in[3];
    const float* b1 = (const float*)d_in[4];
    const float* W2 = (const float*)d_in[5];
    const float* b2 = (const float*)d_in[6];
    float* out = (float*)d_out;

    int E = in_sizes[1] / 2;
    int n = in_sizes[0] / 128;
    const int* src = ei;
    const int* dst = ei + E;

    int nb_n = (n + 255) / 256;
    int nb_e = (E + 255) / 256;
    int nb_s = (n + SCAN_B - 1) / SCAN_B;

    // DEVICE addresses of all __device__ symbols passed as kernel args.
    // (Passing the symbol name directly from host code passes the host
    //  shadow address — on GB300/ATS the kernel silently writes host memory.)
    float* W1hi; cudaGetSymbolAddress((void**)&W1hi, g_W1hi);
    float* W1lo; cudaGetSymbolAddress((void**)&W1lo, g_W1lo);
    float* W2hi; cudaGetSymbolAddress((void**)&W2hi, g_W2hi);
    float* W2lo; cudaGetSymbolAddress((void**)&W2lo, g_W2lo);
    float* h1;   cudaGetSymbolAddress((void**)&h1,   g_h1);
    float* a1;   cudaGetSymbolAddress((void**)&a1,   g_a1);
    float* h2;   cudaGetSymbolAddress((void**)&h2,   g_h2);

    zero_kernel<<<nb_n, 256>>>(n);
    deg_hist_kernel<<<nb_e, 256>>>(dst, w, E);
    convw_kernel<<<64, 256>>>(W1, W1hi, W1lo, 128 * 128);
    convw_kernel<<<32, 256>>>(W2, W2hi, W2lo, 128 * 64);
    dinv_kernel<<<nb_n, 256>>>(n);
    scan_local_kernel<<<nb_s, SCAN_B>>>(n);
    scan_blocks_kernel<<<1, 128>>>(n);
    scan_apply_kernel<<<nb_n, 256>>>(n);
    scatter_kernel<<<nb_e, 256>>>(src, dst, w, E);

    int nb_g = (n + 127) / 128;
    int nb_a = (n + 7) / 8;   // 8 warps per block, 1 warp per node

    gemm_tc_kernel<128, 2, 4><<<nb_g, 256>>>(x, W1hi, W1lo, h1, n);
    agg1_kernel<<<nb_a, 256>>>(b1, n);
    gemm_tc_kernel<64, 4, 2><<<nb_g, 256>>>(a1, W2hi, W2lo, h2, n);
    agg2_kernel<<<nb_a, 256>>>(b2, out, n);
}

// round 5
// speedup vs baseline: 1.1229x; 1.1229x over previous
#include <cuda_runtime.h>
#include <cuda_fp16.h>
#include <cstdint>

#define NN 100000
#define EE 1600000
#define SCAN_B 1024
#define NBLK ((NN + SCAN_B - 1) / SCAN_B)   // 98

// ---------------- scratch (static device arrays; no allocation) ----------------
__device__ float g_deg[NN];
__device__ float g_dinv[NN];
__device__ int   g_cnt[NN];
__device__ int   g_rowptr[NN + 1];
__device__ int   g_fill[NN];
__device__ int   g_blksum[NBLK];
__device__ int   g_blkoff[NBLK + 1];
__device__ unsigned long long g_edge_p[EE];  // packed (src, dinv[src]*w) CSR(dst) order
__device__ __half g_h1[(size_t)NN * 128];
__device__ __half g_a1[(size_t)NN * 128];
__device__ __half g_h2[(size_t)NN * 64];
__device__ float g_W1hi[128 * 128];
__device__ float g_W1lo[128 * 128];
__device__ float g_W2hi[128 * 64];
__device__ float g_W2lo[128 * 64];

// ---------------- tf32 split helpers ----------------
__device__ __forceinline__ void split_tf32(float x, float& hi, float& lo) {
    uint32_t h;
    asm("cvt.rna.tf32.f32 %0, %1;" : "=r"(h) : "f"(x));
    hi = __uint_as_float(h);
    float r = x - hi;                    // exact in fp32
    uint32_t l;
    asm("cvt.rna.tf32.f32 %0, %1;" : "=r"(l) : "f"(r));
    lo = __uint_as_float(l);
}

#define MMA_TF32(c, a, b0, b1)                                            \
    asm volatile("mma.sync.aligned.m16n8k8.row.col.f32.tf32.tf32.f32 "    \
        "{%0,%1,%2,%3}, {%4,%5,%6,%7}, {%8,%9}, {%0,%1,%2,%3};"           \
        : "+f"(c[0]), "+f"(c[1]), "+f"(c[2]), "+f"(c[3])                  \
        : "r"(a[0]), "r"(a[1]), "r"(a[2]), "r"(a[3]), "r"(b0), "r"(b1))

// ---------------- degree + histogram ----------------
__global__ void zero_kernel(int n) {
    int i = blockIdx.x * blockDim.x + threadIdx.x;
    if (i < n) { g_deg[i] = 0.0f; g_cnt[i] = 0; }
}

__global__ void deg_hist_kernel(const int* __restrict__ dst,
                                const float* __restrict__ w, int E) {
    int e = blockIdx.x * blockDim.x + threadIdx.x;
    if (e < E) {
        int d = dst[e];
        atomicAdd(&g_deg[d], w[e]);
        atomicAdd(&g_cnt[d], 1);
    }
}

__global__ void dinv_kernel(int n) {
    int i = blockIdx.x * blockDim.x + threadIdx.x;
    if (i < n) g_dinv[i] = rsqrtf(g_deg[i] + 1.0f);  // +1 = self loop weight
}

// ---------------- W split kernel ----------------
__global__ void convw_kernel(const float* __restrict__ W,
                             float* __restrict__ hi,
                             float* __restrict__ lo, int sz) {
    int i = blockIdx.x * blockDim.x + threadIdx.x;
    if (i < sz) {
        float h, l;
        split_tf32(W[i], h, l);
        hi[i] = h; lo[i] = l;
    }
}

// ---------------- hierarchical scan ----------------
__global__ void scan_local_kernel(int n) {
    __shared__ int warp_sums[32];
    int tid  = threadIdx.x;
    int i    = blockIdx.x * SCAN_B + tid;
    int lane = tid & 31;
    int wid  = tid >> 5;

    int v = (i < n) ? g_cnt[i] : 0;

    int s = v;
    #pragma unroll
    for (int off = 1; off < 32; off <<= 1) {
        int t = __shfl_up_sync(0xffffffffu, s, off);
        if (lane >= off) s += t;
    }
    if (lane == 31) warp_sums[wid] = s;
    __syncthreads();

    if (wid == 0) {
        int ws = warp_sums[lane];
        int sw = ws;
        #pragma unroll
        for (int off = 1; off < 32; off <<= 1) {
            int t = __shfl_up_sync(0xffffffffu, sw, off);
            if (lane >= off) sw += t;
        }
        warp_sums[lane] = sw - ws;  // exclusive
        if (lane == 31 && blockIdx.x < NBLK) g_blksum[blockIdx.x] = sw;
    }
    __syncthreads();

    int excl = s - v + warp_sums[wid];
    if (i < n) g_rowptr[i] = excl;
}

__global__ void scan_blocks_kernel(int n) {
    __shared__ int sh[128];
    int tid = threadIdx.x;  // 128 threads
    int v = (tid < NBLK) ? g_blksum[tid] : 0;
    sh[tid] = v;
    __syncthreads();
    #pragma unroll
    for (int off = 1; off < 128; off <<= 1) {
        int t = (tid >= off) ? sh[tid - off] : 0;
        __syncthreads();
        sh[tid] += t;
        __syncthreads();
    }
    if (tid < NBLK) g_blkoff[tid] = sh[tid] - v;
    if (tid == 127) g_rowptr[n] = sh[127];
}

__global__ void scan_apply_kernel(int n) {
    int i = blockIdx.x * blockDim.x + threadIdx.x;
    if (i < n) {
        int r = g_rowptr[i] + g_blkoff[i >> 10];
        g_rowptr[i] = r;
        g_fill[i]   = r;
    }
}

// ---------------- scatter edges into CSR order (packed 8B) ----------------
__global__ void scatter_kernel(const int* __restrict__ src,
                               const int* __restrict__ dst,
                               const float* __restrict__ w, int E) {
    int e = blockIdx.x * blockDim.x + threadIdx.x;
    if (e < E) {
        int d = dst[e];
        int s = src[e];
        int pos = atomicAdd(&g_fill[d], 1);
        float nm = g_dinv[s] * w[e];
        unsigned long long pk =
            (unsigned long long)(uint32_t)s |
            ((unsigned long long)__float_as_uint(nm) << 32);
        g_edge_p[pos] = pk;
    }
}

// ---------------- GEMM1: C[n,128](fp16) = A[n,128](fp32) @ W (3xTF32) -------
__global__ void __launch_bounds__(256)
gemm1_kernel(const float* __restrict__ A,
             const float* __restrict__ Whi,
             const float* __restrict__ Wlo,
             __half* __restrict__ C, int n) {
    constexpr int OUTD = 128, WARPS_N = 4;
    constexpr int MT = 4, NT = 4;   // WARPS_M=2
    constexpr int KC = 16;
    __shared__ float As_hi[128][KC + 1];
    __shared__ float As_lo[128][KC + 1];
    __shared__ float Bs_hi[KC][OUTD + 4];
    __shared__ float Bs_lo[KC][OUTD + 4];

    int tid  = threadIdx.x;
    int wid  = tid >> 5, lane = tid & 31;
    int wm   = wid / WARPS_N, wn = wid % WARPS_N;
    int g    = lane >> 2, tg = lane & 3;
    int row0 = blockIdx.x * 128;

    float acc[MT][NT][4];
    #pragma unroll
    for (int mi = 0; mi < MT; mi++)
        #pragma unroll
        for (int ni = 0; ni < NT; ni++)
            #pragma unroll
            for (int q = 0; q < 4; q++) acc[mi][ni][q] = 0.f;

    for (int kc = 0; kc < 128; kc += KC) {
        {
            int r  = tid >> 2;   // 0..63
            int c4 = tid & 3;    // 0..3
            #pragma unroll
            for (int h = 0; h < 2; h++) {
                int row  = r + h * 64;
                int grow = row0 + row;
                float4 v = (grow < n)
                    ? *(const float4*)&A[(size_t)grow * 128 + kc + c4 * 4]
                    : make_float4(0.f, 0.f, 0.f, 0.f);
                float hx, lx;
                split_tf32(v.x, hx, lx); As_hi[row][c4*4+0] = hx; As_lo[row][c4*4+0] = lx;
                split_tf32(v.y, hx, lx); As_hi[row][c4*4+1] = hx; As_lo[row][c4*4+1] = lx;
                split_tf32(v.z, hx, lx); As_hi[row][c4*4+2] = hx; As_lo[row][c4*4+2] = lx;
                split_tf32(v.w, hx, lx); As_hi[row][c4*4+3] = hx; As_lo[row][c4*4+3] = lx;
            }
        }
        {
            constexpr int TOT4 = KC * OUTD / 4;
            #pragma unroll
            for (int i = tid; i < TOT4; i += 256) {
                int kk = i / (OUTD / 4), c4 = i % (OUTD / 4);
                *(float4*)&Bs_hi[kk][c4*4] =
                    *(const float4*)&Whi[(size_t)(kc + kk) * OUTD + c4 * 4];
                *(float4*)&Bs_lo[kk][c4*4] =
                    *(const float4*)&Wlo[(size_t)(kc + kk) * OUTD + c4 * 4];
            }
        }
        __syncthreads();
        #pragma unroll
        for (int ks = 0; ks < KC; ks += 8) {
            uint32_t ah[MT][4], al[MT][4];
            #pragma unroll
            for (int mi = 0; mi < MT; mi++) {
                int br = wm * MT * 16 + mi * 16;
                ah[mi][0] = __float_as_uint(As_hi[br + g    ][ks + tg    ]);
                ah[mi][1] = __float_as_uint(As_hi[br + g + 8][ks + tg    ]);
                ah[mi][2] = __float_as_uint(As_hi[br + g    ][ks + tg + 4]);
                ah[mi][3] = __float_as_uint(As_hi[br + g + 8][ks + tg + 4]);
                al[mi][0] = __float_as_uint(As_lo[br + g    ][ks + tg    ]);
                al[mi][1] = __float_as_uint(As_lo[br + g + 8][ks + tg    ]);
                al[mi][2] = __float_as_uint(As_lo[br + g    ][ks + tg + 4]);
                al[mi][3] = __float_as_uint(As_lo[br + g + 8][ks + tg + 4]);
            }
            #pragma unroll
            for (int ni = 0; ni < NT; ni++) {
                int bc = wn * NT * 8 + ni * 8 + g;
                uint32_t bh0 = __float_as_uint(Bs_hi[ks + tg    ][bc]);
                uint32_t bh1 = __float_as_uint(Bs_hi[ks + tg + 4][bc]);
                uint32_t bl0 = __float_as_uint(Bs_lo[ks + tg    ][bc]);
                uint32_t bl1 = __float_as_uint(Bs_lo[ks + tg + 4][bc]);
                #pragma unroll
                for (int mi = 0; mi < MT; mi++) {
                    MMA_TF32(acc[mi][ni], ah[mi], bh0, bh1);
                    MMA_TF32(acc[mi][ni], ah[mi], bl0, bl1);
                    MMA_TF32(acc[mi][ni], al[mi], bh0, bh1);
                }
            }
        }
        __syncthreads();
    }
    #pragma unroll
    for (int mi = 0; mi < MT; mi++) {
        #pragma unroll
        for (int ni = 0; ni < NT; ni++) {
            int row = row0 + wm * MT * 16 + mi * 16 + g;
            int col = wn * NT * 8 + ni * 8 + tg * 2;
            if (row < n) {
                __half2 v0 = __floats2half2_rn(acc[mi][ni][0], acc[mi][ni][1]);
                *(__half2*)&C[(size_t)row * OUTD + col] = v0;
            }
            if (row + 8 < n) {
                __half2 v1 = __floats2half2_rn(acc[mi][ni][2], acc[mi][ni][3]);
                *(__half2*)&C[(size_t)(row + 8) * OUTD + col] = v1;
            }
        }
    }
}

// ---------------- GEMM2: C[n,64](fp16) = A[n,128](fp16) @ W (2xTF32) --------
// fp16 is exact in tf32 -> no A split; only W hi/lo passes.
__global__ void __launch_bounds__(256)
gemm2_kernel(const __half* __restrict__ A,
             const float* __restrict__ Whi,
             const float* __restrict__ Wlo,
             __half* __restrict__ C, int n) {
    constexpr int OUTD = 64, WARPS_N = 2;
    constexpr int MT = 2, NT = 4;   // WARPS_M=4
    constexpr int KC = 16;
    __shared__ float As[128][KC + 1];
    __shared__ float Bs_hi[KC][OUTD + 4];
    __shared__ float Bs_lo[KC][OUTD + 4];

    int tid  = threadIdx.x;
    int wid  = tid >> 5, lane = tid & 31;
    int wm   = wid / WARPS_N, wn = wid % WARPS_N;
    int g    = lane >> 2, tg = lane & 3;
    int row0 = blockIdx.x * 128;

    float acc[MT][NT][4];
    #pragma unroll
    for (int mi = 0; mi < MT; mi++)
        #pragma unroll
        for (int ni = 0; ni < NT; ni++)
            #pragma unroll
            for (int q = 0; q < 4; q++) acc[mi][ni][q] = 0.f;

    for (int kc = 0; kc < 128; kc += KC) {
        {
            int r  = tid >> 1;   // 0..127
            int hh = tid & 1;    // 0..1
            int grow = row0 + r;
            uint4 v = make_uint4(0, 0, 0, 0);
            if (grow < n)
                v = *(const uint4*)&A[(size_t)grow * 128 + kc + hh * 8];
            const __half2* hp = (const __half2*)&v;
            #pragma unroll
            for (int j = 0; j < 4; j++) {
                float2 f = __half22float2(hp[j]);
                As[r][hh*8 + j*2    ] = f.x;
                As[r][hh*8 + j*2 + 1] = f.y;
            }
        }
        {
            constexpr int TOT4 = KC * OUTD / 4;
            #pragma unroll
            for (int i = tid; i < TOT4; i += 256) {
                int kk = i / (OUTD / 4), c4 = i % (OUTD / 4);
                *(float4*)&Bs_hi[kk][c4*4] =
                    *(const float4*)&Whi[(size_t)(kc + kk) * OUTD + c4 * 4];
                *(float4*)&Bs_lo[kk][c4*4] =
                    *(const float4*)&Wlo[(size_t)(kc + kk) * OUTD + c4 * 4];
            }
        }
        __syncthreads();
        #pragma unroll
        for (int ks = 0; ks < KC; ks += 8) {
            uint32_t ah[MT][4];
            #pragma unroll
            for (int mi = 0; mi < MT; mi++) {
                int br = wm * MT * 16 + mi * 16;
                ah[mi][0] = __float_as_uint(As[br + g    ][ks + tg    ]);
                ah[mi][1] = __float_as_uint(As[br + g + 8][ks + tg    ]);
                ah[mi][2] = __float_as_uint(As[br + g    ][ks + tg + 4]);
                ah[mi][3] = __float_as_uint(As[br + g + 8][ks + tg + 4]);
            }
            #pragma unroll
            for (int ni = 0; ni < NT; ni++) {
                int bc = wn * NT * 8 + ni * 8 + g;
                uint32_t bh0 = __float_as_uint(Bs_hi[ks + tg    ][bc]);
                uint32_t bh1 = __float_as_uint(Bs_hi[ks + tg + 4][bc]);
                uint32_t bl0 = __float_as_uint(Bs_lo[ks + tg    ][bc]);
                uint32_t bl1 = __float_as_uint(Bs_lo[ks + tg + 4][bc]);
                #pragma unroll
                for (int mi = 0; mi < MT; mi++) {
                    MMA_TF32(acc[mi][ni], ah[mi], bh0, bh1);
                    MMA_TF32(acc[mi][ni], ah[mi], bl0, bl1);
                }
            }
        }
        __syncthreads();
    }
    #pragma unroll
    for (int mi = 0; mi < MT; mi++) {
        #pragma unroll
        for (int ni = 0; ni < NT; ni++) {
            int row = row0 + wm * MT * 16 + mi * 16 + g;
            int col = wn * NT * 8 + ni * 8 + tg * 2;
            if (row < n) {
                __half2 v0 = __floats2half2_rn(acc[mi][ni][0], acc[mi][ni][1]);
                *(__half2*)&C[(size_t)row * OUTD + col] = v0;
            }
            if (row + 8 < n) {
                __half2 v1 = __floats2half2_rn(acc[mi][ni][2], acc[mi][ni][3]);
                *(__half2*)&C[(size_t)(row + 8) * OUTD + col] = v1;
            }
        }
    }
}

// ---------------- CSR aggregation (fp16 rows): one warp per node ------------
__device__ __forceinline__ void gather_row128(const __half* __restrict__ h,
                                              int s, int lane, float nm,
                                              float acc[4]) {
    uint2 rv = *(const uint2*)&h[(size_t)s * 128 + lane * 4];
    __half2 p0 = *reinterpret_cast<__half2*>(&rv.x);
    __half2 p1 = *reinterpret_cast<__half2*>(&rv.y);
    float2 f0 = __half22float2(p0);
    float2 f1 = __half22float2(p1);
    acc[0] += nm * f0.x; acc[1] += nm * f0.y;
    acc[2] += nm * f1.x; acc[3] += nm * f1.y;
}

__global__ void agg1_kernel(const float* __restrict__ bias, int n) {
    int gwarp = (blockIdx.x * blockDim.x + threadIdx.x) >> 5;
    int lane  = threadIdx.x & 31;
    if (gwarp >= n) return;
    int node = gwarp;

    float dv = g_dinv[node];
    float acc[4] = {0.f, 0.f, 0.f, 0.f};

    int beg = g_rowptr[node];
    int end = g_rowptr[node + 1];
    int e = beg;
    for (; e + 1 < end; e += 2) {
        unsigned long long p0 = g_edge_p[e];
        unsigned long long p1 = g_edge_p[e + 1];
        int   s0 = (int)(uint32_t)p0;
        int   s1 = (int)(uint32_t)p1;
        float n0 = __uint_as_float((uint32_t)(p0 >> 32)) * dv;
        float n1 = __uint_as_float((uint32_t)(p1 >> 32)) * dv;
        gather_row128(g_h1, s0, lane, n0, acc);
        gather_row128(g_h1, s1, lane, n1, acc);
    }
    if (e < end) {
        unsigned long long p0 = g_edge_p[e];
        int   s0 = (int)(uint32_t)p0;
        float n0 = __uint_as_float((uint32_t)(p0 >> 32)) * dv;
        gather_row128(g_h1, s0, lane, n0, acc);
    }
    gather_row128(g_h1, node, lane, dv * dv, acc);   // self loop

    float r0 = fmaxf(acc[0] + bias[lane*4+0], 0.f);
    float r1 = fmaxf(acc[1] + bias[lane*4+1], 0.f);
    float r2 = fmaxf(acc[2] + bias[lane*4+2], 0.f);
    float r3 = fmaxf(acc[3] + bias[lane*4+3], 0.f);
    uint2 ov;
    __half2 o0 = __floats2half2_rn(r0, r1);
    __half2 o1 = __floats2half2_rn(r2, r3);
    ov.x = *reinterpret_cast<uint32_t*>(&o0);
    ov.y = *reinterpret_cast<uint32_t*>(&o1);
    *(uint2*)&g_a1[(size_t)node * 128 + lane * 4] = ov;
}

__device__ __forceinline__ void gather_row64(const __half* __restrict__ h,
                                             int s, int lane, float nm,
                                             float acc[2]) {
    uint32_t rv = *(const uint32_t*)&h[(size_t)s * 64 + lane * 2];
    __half2 p0 = *reinterpret_cast<__half2*>(&rv);
    float2 f0 = __half22float2(p0);
    acc[0] += nm * f0.x; acc[1] += nm * f0.y;
}

__global__ void agg2_kernel(const float* __restrict__ bias,
                            float* __restrict__ out, int n) {
    int gwarp = (blockIdx.x * blockDim.x + threadIdx.x) >> 5;
    int lane  = threadIdx.x & 31;
    if (gwarp >= n) return;
    int node = gwarp;

    float dv = g_dinv[node];
    float acc[2] = {0.f, 0.f};

    int beg = g_rowptr[node];
    int end = g_rowptr[node + 1];
    int e = beg;
    for (; e + 1 < end; e += 2) {
        unsigned long long p0 = g_edge_p[e];
        unsigned long long p1 = g_edge_p[e + 1];
        int   s0 = (int)(uint32_t)p0;
        int   s1 = (int)(uint32_t)p1;
        float n0 = __uint_as_float((uint32_t)(p0 >> 32)) * dv;
        float n1 = __uint_as_float((uint32_t)(p1 >> 32)) * dv;
        gather_row64(g_h2, s0, lane, n0, acc);
        gather_row64(g_h2, s1, lane, n1, acc);
    }
    if (e < end) {
        unsigned long long p0 = g_edge_p[e];
        int   s0 = (int)(uint32_t)p0;
        float n0 = __uint_as_float((uint32_t)(p0 >> 32)) * dv;
        gather_row64(g_h2, s0, lane, n0, acc);
    }
    gather_row64(g_h2, node, lane, dv * dv, acc);   // self loop

    float2 r;
    r.x = acc[0] + bias[lane*2+0];
    r.y = acc[1] + bias[lane*2+1];
    *(float2*)&out[(size_t)node * 64 + lane * 2] = r;
}

// ---------------- launch ----------------
extern "C" void kernel_launch(void* const* d_in, const int* in_sizes, int n_in,
                              void* d_out, int out_size) {
    const float* x  = (const float*)d_in[0];
    const int*   ei = (const int*)  d_in[1];
    const float* w  = (const float*)d_in[2];
    const float* W1 = (const float*)d_in[3];
    const float* b1 = (const float*)d_in[4];
    const float* W2 = (const float*)d_in[5];
    const float* b2 = (const float*)d_in[6];
    float* out = (float*)d_out;

    int E = in_sizes[1] / 2;
    int n = in_sizes[0] / 128;
    const int* src = ei;
    const int* dst = ei + E;

    int nb_n = (n + 255) / 256;
    int nb_e = (E + 255) / 256;
    int nb_s = (n + SCAN_B - 1) / SCAN_B;

    // device addresses of __device__ symbols used as kernel args
    float*  W1hi; cudaGetSymbolAddress((void**)&W1hi, g_W1hi);
    float*  W1lo; cudaGetSymbolAddress((void**)&W1lo, g_W1lo);
    float*  W2hi; cudaGetSymbolAddress((void**)&W2hi, g_W2hi);
    float*  W2lo; cudaGetSymbolAddress((void**)&W2lo, g_W2lo);
    __half* h1;   cudaGetSymbolAddress((void**)&h1,   g_h1);
    __half* a1;   cudaGetSymbolAddress((void**)&a1,   g_a1);
    __half* h2;   cudaGetSymbolAddress((void**)&h2,   g_h2);

    int nb_g = (n + 127) / 128;
    int nb_a = (n + 7) / 8;   // 8 warps per block, 1 warp per node

    // gemm1 placed 4th so ncu (-s-based capture) profiles it next round
    convw_kernel<<<64, 256>>>(W1, W1hi, W1lo, 128 * 128);     // 1
    convw_kernel<<<32, 256>>>(W2, W2hi, W2lo, 128 * 64);      // 2
    zero_kernel<<<nb_n, 256>>>(n);                            // 3
    gemm1_kernel<<<nb_g, 256>>>(x, W1hi, W1lo, h1, n);        // 4  <- profiled
    deg_hist_kernel<<<nb_e, 256>>>(dst, w, E);                // 5
    dinv_kernel<<<nb_n, 256>>>(n);                            // 6
    scan_local_kernel<<<nb_s, SCAN_B>>>(n);                   // 7
    scan_blocks_kernel<<<1, 128>>>(n);                        // 8
    scan_apply_kernel<<<nb_n, 256>>>(n);                      // 9
    scatter_kernel<<<nb_e, 256>>>(src, dst, w, E);            // 10
    agg1_kernel<<<nb_a, 256>>>(b1, n);                        // 11
    gemm2_kernel<<<nb_g, 256>>>(a1, W2hi, W2lo, h2, n);       // 12
    agg2_kernel<<<nb_a, 256>>>(b2, out, n);                   // 13
}

// round 6
// speedup vs baseline: 1.6178x; 1.4407x over previous
#include <cuda_runtime.h>
#include <cuda_fp16.h>
#include <cstdint>

#define NN 100000
#define EE 1600000
#define SCAN_B 1024
#define NBLK ((NN + SCAN_B - 1) / SCAN_B)   // 98

// ---------------- scratch (static device arrays; no allocation) ----------------
__device__ float g_deg[NN];
__device__ float g_dinv[NN];
__device__ int   g_cnt[NN];
__device__ int   g_rowptr[NN + 1];
__device__ int   g_fill[NN];
__device__ int   g_blksum[NBLK];
__device__ int   g_blkoff[NBLK + 1];
__device__ unsigned long long g_edge_p[EE];  // packed (src, dinv[src]*w) CSR(dst) order
__device__ __half g_h1[(size_t)NN * 128];
__device__ __half g_a1[(size_t)NN * 128];
__device__ __half g_h2[(size_t)NN * 64];
__device__ __half g_W1h[128 * 128];   // W1 transposed [n][k], fp16
__device__ __half g_W2h[64 * 128];    // W2 transposed [n][k], fp16

// ---------------- fp16 HMMA macro (m16n8k16, fp32 accum) ----------------
#define MMA_F16(c, a, b0, b1)                                             \
    asm volatile("mma.sync.aligned.m16n8k16.row.col.f32.f16.f16.f32 "     \
        "{%0,%1,%2,%3}, {%4,%5,%6,%7}, {%8,%9}, {%0,%1,%2,%3};"           \
        : "+f"(c[0]), "+f"(c[1]), "+f"(c[2]), "+f"(c[3])                  \
        : "r"(a[0]), "r"(a[1]), "r"(a[2]), "r"(a[3]), "r"(b0), "r"(b1))

// ---------------- degree + histogram ----------------
__global__ void zero_kernel(int n) {
    int i = blockIdx.x * blockDim.x + threadIdx.x;
    if (i < n) { g_deg[i] = 0.0f; g_cnt[i] = 0; }
}

__global__ void deg_hist_kernel(const int* __restrict__ dst,
                                const float* __restrict__ w, int E) {
    int e = blockIdx.x * blockDim.x + threadIdx.x;
    if (e < E) {
        int d = dst[e];
        atomicAdd(&g_deg[d], w[e]);
        atomicAdd(&g_cnt[d], 1);
    }
}

__global__ void dinv_kernel(int n) {
    int i = blockIdx.x * blockDim.x + threadIdx.x;
    if (i < n) g_dinv[i] = rsqrtf(g_deg[i] + 1.0f);  // +1 = self loop weight
}

// ---------------- W convert kernels: fp32 [k][n] -> fp16 transposed [n][k] ---
__global__ void convw1_kernel(const float* __restrict__ W,
                              __half* __restrict__ Wt) {
    int i = blockIdx.x * blockDim.x + threadIdx.x;  // i = n*128 + k
    if (i < 128 * 128) {
        int nn = i >> 7, kk = i & 127;
        Wt[i] = __float2half_rn(W[kk * 128 + nn]);
    }
}
__global__ void convw2_kernel(const float* __restrict__ W,
                              __half* __restrict__ Wt) {
    int i = blockIdx.x * blockDim.x + threadIdx.x;  // i = n*128 + k
    if (i < 64 * 128) {
        int nn = i >> 7, kk = i & 127;
        Wt[i] = __float2half_rn(W[kk * 64 + nn]);
    }
}

// ---------------- hierarchical scan ----------------
__global__ void scan_local_kernel(int n) {
    __shared__ int warp_sums[32];
    int tid  = threadIdx.x;
    int i    = blockIdx.x * SCAN_B + tid;
    int lane = tid & 31;
    int wid  = tid >> 5;

    int v = (i < n) ? g_cnt[i] : 0;

    int s = v;
    #pragma unroll
    for (int off = 1; off < 32; off <<= 1) {
        int t = __shfl_up_sync(0xffffffffu, s, off);
        if (lane >= off) s += t;
    }
    if (lane == 31) warp_sums[wid] = s;
    __syncthreads();

    if (wid == 0) {
        int ws = warp_sums[lane];
        int sw = ws;
        #pragma unroll
        for (int off = 1; off < 32; off <<= 1) {
            int t = __shfl_up_sync(0xffffffffu, sw, off);
            if (lane >= off) sw += t;
        }
        warp_sums[lane] = sw - ws;  // exclusive
        if (lane == 31 && blockIdx.x < NBLK) g_blksum[blockIdx.x] = sw;
    }
    __syncthreads();

    int excl = s - v + warp_sums[wid];
    if (i < n) g_rowptr[i] = excl;
}

__global__ void scan_blocks_kernel(int n) {
    __shared__ int sh[128];
    int tid = threadIdx.x;  // 128 threads
    int v = (tid < NBLK) ? g_blksum[tid] : 0;
    sh[tid] = v;
    __syncthreads();
    #pragma unroll
    for (int off = 1; off < 128; off <<= 1) {
        int t = (tid >= off) ? sh[tid - off] : 0;
        __syncthreads();
        sh[tid] += t;
        __syncthreads();
    }
    if (tid < NBLK) g_blkoff[tid] = sh[tid] - v;
    if (tid == 127) g_rowptr[n] = sh[127];
}

__global__ void scan_apply_kernel(int n) {
    int i = blockIdx.x * blockDim.x + threadIdx.x;
    if (i < n) {
        int r = g_rowptr[i] + g_blkoff[i >> 10];
        g_rowptr[i] = r;
        g_fill[i]   = r;
    }
}

// ---------------- scatter edges into CSR order (packed 8B) ----------------
__global__ void scatter_kernel(const int* __restrict__ src,
                               const int* __restrict__ dst,
                               const float* __restrict__ w, int E) {
    int e = blockIdx.x * blockDim.x + threadIdx.x;
    if (e < E) {
        int d = dst[e];
        int s = src[e];
        int pos = atomicAdd(&g_fill[d], 1);
        float nm = g_dinv[s] * w[e];
        unsigned long long pk =
            (unsigned long long)(uint32_t)s |
            ((unsigned long long)__float_as_uint(nm) << 32);
        g_edge_p[pos] = pk;
    }
}

// ---------------- GEMM1: C[n,128](fp16) = A[n,128](fp32) @ W1h^T (HMMA) -----
// A converted fp32->fp16 during smem load. B = W1 fp16 transposed [n][k].
__global__ void __launch_bounds__(256, 2)
gemm1_kernel(const float* __restrict__ A,
             const __half* __restrict__ Bt,   // [128][128] = [n][k]
             __half* __restrict__ C, int n) {
    constexpr int KC = 32;
    constexpr int LDS_K = KC + 8;   // 40 halves = 80 bytes (16B-aligned stride)
    __shared__ __half As[128][LDS_K];
    __shared__ __half Bs[128][LDS_K];

    int tid  = threadIdx.x;
    int wid  = tid >> 5, lane = tid & 31;
    int wm   = wid >> 2, wn = wid & 3;     // 2 x 4 warps
    int g    = lane >> 2, tg = lane & 3;
    int row0 = blockIdx.x * 128;

    float acc[4][4][4];   // MT=4 m16 tiles, NT=4 n8 tiles
    #pragma unroll
    for (int mi = 0; mi < 4; mi++)
        #pragma unroll
        for (int ni = 0; ni < 4; ni++)
            #pragma unroll
            for (int q = 0; q < 4; q++) acc[mi][ni][q] = 0.f;

    for (int kc = 0; kc < 128; kc += KC) {
        // A chunk: 128 rows x 32 k, fp32 -> fp16
        {
            int r  = tid >> 1;     // 0..127
            int hf = tid & 1;      // 0..1 -> k-halves of 16
            int grow = row0 + r;
            #pragma unroll
            for (int j = 0; j < 4; j++) {
                float4 v = make_float4(0.f, 0.f, 0.f, 0.f);
                if (grow < n)
                    v = *(const float4*)&A[(size_t)grow * 128 + kc + hf * 16 + j * 4];
                __half2 h0 = __floats2half2_rn(v.x, v.y);
                __half2 h1 = __floats2half2_rn(v.z, v.w);
                uint2 pk;
                pk.x = *reinterpret_cast<uint32_t*>(&h0);
                pk.y = *reinterpret_cast<uint32_t*>(&h1);
                *(uint2*)&As[r][hf * 16 + j * 4] = pk;
            }
        }
        // B chunk: 128 n x 32 k fp16 (already transposed in global)
        {
            #pragma unroll
            for (int i = tid; i < 128 * 4; i += 256) {
                int nn = i >> 2, q = i & 3;
                uint4 v = *(const uint4*)&Bt[(size_t)nn * 128 + kc + q * 8];
                *(uint4*)&Bs[nn][q * 8] = v;
            }
        }
        __syncthreads();
        #pragma unroll
        for (int ks = 0; ks < KC; ks += 16) {
            uint32_t a[4][4];
            #pragma unroll
            for (int mi = 0; mi < 4; mi++) {
                int br = wm * 64 + mi * 16;
                a[mi][0] = *(uint32_t*)&As[br + g    ][ks + tg * 2    ];
                a[mi][1] = *(uint32_t*)&As[br + g + 8][ks + tg * 2    ];
                a[mi][2] = *(uint32_t*)&As[br + g    ][ks + tg * 2 + 8];
                a[mi][3] = *(uint32_t*)&As[br + g + 8][ks + tg * 2 + 8];
            }
            #pragma unroll
            for (int ni = 0; ni < 4; ni++) {
                int col = wn * 32 + ni * 8 + g;
                uint32_t b0 = *(uint32_t*)&Bs[col][ks + tg * 2    ];
                uint32_t b1 = *(uint32_t*)&Bs[col][ks + tg * 2 + 8];
                #pragma unroll
                for (int mi = 0; mi < 4; mi++)
                    MMA_F16(acc[mi][ni], a[mi], b0, b1);
            }
        }
        __syncthreads();
    }
    #pragma unroll
    for (int mi = 0; mi < 4; mi++) {
        #pragma unroll
        for (int ni = 0; ni < 4; ni++) {
            int row = row0 + wm * 64 + mi * 16 + g;
            int col = wn * 32 + ni * 8 + tg * 2;
            if (row < n) {
                __half2 v0 = __floats2half2_rn(acc[mi][ni][0], acc[mi][ni][1]);
                *(__half2*)&C[(size_t)row * 128 + col] = v0;
            }
            if (row + 8 < n) {
                __half2 v1 = __floats2half2_rn(acc[mi][ni][2], acc[mi][ni][3]);
                *(__half2*)&C[(size_t)(row + 8) * 128 + col] = v1;
            }
        }
    }
}

// ---------------- GEMM2: C[n,64](fp16) = A[n,128](fp16) @ W2h^T (HMMA) ------
__global__ void __launch_bounds__(256, 2)
gemm2_kernel(const __half* __restrict__ A,
             const __half* __restrict__ Bt,   // [64][128] = [n][k]
             __half* __restrict__ C, int n) {
    constexpr int KC = 32;
    constexpr int LDS_K = KC + 8;
    __shared__ __half As[128][LDS_K];
    __shared__ __half Bs[64][LDS_K];

    int tid  = threadIdx.x;
    int wid  = tid >> 5, lane = tid & 31;
    int wm   = wid >> 1, wn = wid & 1;     // 4 x 2 warps
    int g    = lane >> 2, tg = lane & 3;
    int row0 = blockIdx.x * 128;

    float acc[2][4][4];   // MT=2, NT=4
    #pragma unroll
    for (int mi = 0; mi < 2; mi++)
        #pragma unroll
        for (int ni = 0; ni < 4; ni++)
            #pragma unroll
            for (int q = 0; q < 4; q++) acc[mi][ni][q] = 0.f;

    for (int kc = 0; kc < 128; kc += KC) {
        // A chunk: 128 rows x 32 k fp16
        {
            int r  = tid >> 1;
            int hf = tid & 1;
            int grow = row0 + r;
            #pragma unroll
            for (int j = 0; j < 2; j++) {
                uint4 v = make_uint4(0, 0, 0, 0);
                if (grow < n)
                    v = *(const uint4*)&A[(size_t)grow * 128 + kc + hf * 16 + j * 8];
                *(uint4*)&As[r][hf * 16 + j * 8] = v;
            }
        }
        // B chunk: 64 n x 32 k fp16
        {
            int i = tid;   // 64*4 = 256 loads
            int nn = i >> 2, q = i & 3;
            uint4 v = *(const uint4*)&Bt[(size_t)nn * 128 + kc + q * 8];
            *(uint4*)&Bs[nn][q * 8] = v;
        }
        __syncthreads();
        #pragma unroll
        for (int ks = 0; ks < KC; ks += 16) {
            uint32_t a[2][4];
            #pragma unroll
            for (int mi = 0; mi < 2; mi++) {
                int br = wm * 32 + mi * 16;
                a[mi][0] = *(uint32_t*)&As[br + g    ][ks + tg * 2    ];
                a[mi][1] = *(uint32_t*)&As[br + g + 8][ks + tg * 2    ];
                a[mi][2] = *(uint32_t*)&As[br + g    ][ks + tg * 2 + 8];
                a[mi][3] = *(uint32_t*)&As[br + g + 8][ks + tg * 2 + 8];
            }
            #pragma unroll
            for (int ni = 0; ni < 4; ni++) {
                int col = wn * 32 + ni * 8 + g;
                uint32_t b0 = *(uint32_t*)&Bs[col][ks + tg * 2    ];
                uint32_t b1 = *(uint32_t*)&Bs[col][ks + tg * 2 + 8];
                #pragma unroll
                for (int mi = 0; mi < 2; mi++)
                    MMA_F16(acc[mi][ni], a[mi], b0, b1);
            }
        }
        __syncthreads();
    }
    #pragma unroll
    for (int mi = 0; mi < 2; mi++) {
        #pragma unroll
        for (int ni = 0; ni < 4; ni++) {
            int row = row0 + wm * 32 + mi * 16 + g;
            int col = wn * 32 + ni * 8 + tg * 2;
            if (row < n) {
                __half2 v0 = __floats2half2_rn(acc[mi][ni][0], acc[mi][ni][1]);
                *(__half2*)&C[(size_t)row * 64 + col] = v0;
            }
            if (row + 8 < n) {
                __half2 v1 = __floats2half2_rn(acc[mi][ni][2], acc[mi][ni][3]);
                *(__half2*)&C[(size_t)(row + 8) * 64 + col] = v1;
            }
        }
    }
}

// ---------------- CSR aggregation (fp16 rows): one warp per node ------------
__device__ __forceinline__ void gather_row128(const __half* __restrict__ h,
                                              int s, int lane, float nm,
                                              float acc[4]) {
    uint2 rv = *(const uint2*)&h[(size_t)s * 128 + lane * 4];
    __half2 p0 = *reinterpret_cast<__half2*>(&rv.x);
    __half2 p1 = *reinterpret_cast<__half2*>(&rv.y);
    float2 f0 = __half22float2(p0);
    float2 f1 = __half22float2(p1);
    acc[0] += nm * f0.x; acc[1] += nm * f0.y;
    acc[2] += nm * f1.x; acc[3] += nm * f1.y;
}

__global__ void agg1_kernel(const float* __restrict__ bias, int n) {
    int gwarp = (blockIdx.x * blockDim.x + threadIdx.x) >> 5;
    int lane  = threadIdx.x & 31;
    if (gwarp >= n) return;
    int node = gwarp;

    float dv = g_dinv[node];
    float acc[4] = {0.f, 0.f, 0.f, 0.f};

    int beg = g_rowptr[node];
    int end = g_rowptr[node + 1];
    int e = beg;
    for (; e + 1 < end; e += 2) {
        unsigned long long p0 = g_edge_p[e];
        unsigned long long p1 = g_edge_p[e + 1];
        int   s0 = (int)(uint32_t)p0;
        int   s1 = (int)(uint32_t)p1;
        float n0 = __uint_as_float((uint32_t)(p0 >> 32)) * dv;
        float n1 = __uint_as_float((uint32_t)(p1 >> 32)) * dv;
        gather_row128(g_h1, s0, lane, n0, acc);
        gather_row128(g_h1, s1, lane, n1, acc);
    }
    if (e < end) {
        unsigned long long p0 = g_edge_p[e];
        int   s0 = (int)(uint32_t)p0;
        float n0 = __uint_as_float((uint32_t)(p0 >> 32)) * dv;
        gather_row128(g_h1, s0, lane, n0, acc);
    }
    gather_row128(g_h1, node, lane, dv * dv, acc);   // self loop

    float r0 = fmaxf(acc[0] + bias[lane*4+0], 0.f);
    float r1 = fmaxf(acc[1] + bias[lane*4+1], 0.f);
    float r2 = fmaxf(acc[2] + bias[lane*4+2], 0.f);
    float r3 = fmaxf(acc[3] + bias[lane*4+3], 0.f);
    uint2 ov;
    __half2 o0 = __floats2half2_rn(r0, r1);
    __half2 o1 = __floats2half2_rn(r2, r3);
    ov.x = *reinterpret_cast<uint32_t*>(&o0);
    ov.y = *reinterpret_cast<uint32_t*>(&o1);
    *(uint2*)&g_a1[(size_t)node * 128 + lane * 4] = ov;
}

__device__ __forceinline__ void gather_row64(const __half* __restrict__ h,
                                             int s, int lane, float nm,
                                             float acc[2]) {
    uint32_t rv = *(const uint32_t*)&h[(size_t)s * 64 + lane * 2];
    __half2 p0 = *reinterpret_cast<__half2*>(&rv);
    float2 f0 = __half22float2(p0);
    acc[0] += nm * f0.x; acc[1] += nm * f0.y;
}

__global__ void agg2_kernel(const float* __restrict__ bias,
                            float* __restrict__ out, int n) {
    int gwarp = (blockIdx.x * blockDim.x + threadIdx.x) >> 5;
    int lane  = threadIdx.x & 31;
    if (gwarp >= n) return;
    int node = gwarp;

    float dv = g_dinv[node];
    float acc[2] = {0.f, 0.f};

    int beg = g_rowptr[node];
    int end = g_rowptr[node + 1];
    int e = beg;
    for (; e + 1 < end; e += 2) {
        unsigned long long p0 = g_edge_p[e];
        unsigned long long p1 = g_edge_p[e + 1];
        int   s0 = (int)(uint32_t)p0;
        int   s1 = (int)(uint32_t)p1;
        float n0 = __uint_as_float((uint32_t)(p0 >> 32)) * dv;
        float n1 = __uint_as_float((uint32_t)(p1 >> 32)) * dv;
        gather_row64(g_h2, s0, lane, n0, acc);
        gather_row64(g_h2, s1, lane, n1, acc);
    }
    if (e < end) {
        unsigned long long p0 = g_edge_p[e];
        int   s0 = (int)(uint32_t)p0;
        float n0 = __uint_as_float((uint32_t)(p0 >> 32)) * dv;
        gather_row64(g_h2, s0, lane, n0, acc);
    }
    gather_row64(g_h2, node, lane, dv * dv, acc);   // self loop

    float2 r;
    r.x = acc[0] + bias[lane*2+0];
    r.y = acc[1] + bias[lane*2+1];
    *(float2*)&out[(size_t)node * 64 + lane * 2] = r;
}

// ---------------- launch ----------------
extern "C" void kernel_launch(void* const* d_in, const int* in_sizes, int n_in,
                              void* d_out, int out_size) {
    const float* x  = (const float*)d_in[0];
    const int*   ei = (const int*)  d_in[1];
    const float* w  = (const float*)d_in[2];
    const float* W1 = (const float*)d_in[3];
    const float* b1 = (const float*)d_in[4];
    const float* W2 = (const float*)d_in[5];
    const float* b2 = (const float*)d_in[6];
    float* out = (float*)d_out;

    int E = in_sizes[1] / 2;
    int n = in_sizes[0] / 128;
    const int* src = ei;
    const int* dst = ei + E;

    int nb_n = (n + 255) / 256;
    int nb_e = (E + 255) / 256;
    int nb_s = (n + SCAN_B - 1) / SCAN_B;

    // device addresses of __device__ symbols used as kernel args
    __half* W1h; cudaGetSymbolAddress((void**)&W1h, g_W1h);
    __half* W2h; cudaGetSymbolAddress((void**)&W2h, g_W2h);
    __half* h1;  cudaGetSymbolAddress((void**)&h1,  g_h1);
    __half* a1;  cudaGetSymbolAddress((void**)&a1,  g_a1);
    __half* h2;  cudaGetSymbolAddress((void**)&h2,  g_h2);

    int nb_g = (n + 127) / 128;
    int nb_a = (n + 7) / 8;   // 8 warps per block, 1 warp per node

    // gemm1 stays 4th so ncu profiles it
    convw1_kernel<<<64, 256>>>(W1, W1h);                      // 1
    convw2_kernel<<<32, 256>>>(W2, W2h);                      // 2
    zero_kernel<<<nb_n, 256>>>(n);                            // 3
    gemm1_kernel<<<nb_g, 256>>>(x, W1h, h1, n);               // 4  <- profiled
    deg_hist_kernel<<<nb_e, 256>>>(dst, w, E);                // 5
    dinv_kernel<<<nb_n, 256>>>(n);                            // 6
    scan_local_kernel<<<nb_s, SCAN_B>>>(n);                   // 7
    scan_blocks_kernel<<<1, 128>>>(n);                        // 8
    scan_apply_kernel<<<nb_n, 256>>>(n);                      // 9
    scatter_kernel<<<nb_e, 256>>>(src, dst, w, E);            // 10
    agg1_kernel<<<nb_a, 256>>>(b1, n);                        // 11
    gemm2_kernel<<<nb_g, 256>>>(a1, W2h, h2, n);              // 12
    agg2_kernel<<<nb_a, 256>>>(b2, out, n);                   // 13
}

// round 7
// speedup vs baseline: 1.6239x; 1.0037x over previous
#include <cuda_runtime.h>
#include <cuda_fp16.h>
#include <cstdint>

#define NN 100000
#define EE 1600000
#define SCAN_B 1024
#define NBLK ((NN + SCAN_B - 1) / SCAN_B)   // 98

// ---------------- scratch (static device arrays; no allocation) ----------------
__device__ float g_deg[NN];
__device__ float g_dinv[NN];
__device__ int   g_cnt[NN];
__device__ int   g_rowptr[NN + 1];
__device__ int   g_fill[NN];
__device__ int   g_blksum[NBLK];
__device__ int   g_blkoff[NBLK + 1];
__device__ unsigned long long g_edge_p[EE];  // packed (src, dinv[src]*w) CSR(dst) order
__device__ __half g_h1[(size_t)NN * 128];
__device__ __half g_a1[(size_t)NN * 128];
__device__ __half g_h2[(size_t)NN * 64];
__device__ __half g_W1h[128 * 128];   // W1 transposed [n][k], fp16
__device__ __half g_W2h[64 * 128];    // W2 transposed [n][k], fp16

// ---------------- fp16 HMMA macro (m16n8k16, fp32 accum) ----------------
#define MMA_F16(c, a, b0, b1)                                             \
    asm volatile("mma.sync.aligned.m16n8k16.row.col.f32.f16.f16.f32 "     \
        "{%0,%1,%2,%3}, {%4,%5,%6,%7}, {%8,%9}, {%0,%1,%2,%3};"           \
        : "+f"(c[0]), "+f"(c[1]), "+f"(c[2]), "+f"(c[3])                  \
        : "r"(a[0]), "r"(a[1]), "r"(a[2]), "r"(a[3]), "r"(b0), "r"(b1))

// ---------------- degree + histogram ----------------
__global__ void zero_kernel(int n) {
    int i = blockIdx.x * blockDim.x + threadIdx.x;
    if (i < n) { g_deg[i] = 0.0f; g_cnt[i] = 0; }
}

__global__ void deg_hist_kernel(const int* __restrict__ dst,
                                const float* __restrict__ w, int E) {
    int e = blockIdx.x * blockDim.x + threadIdx.x;
    if (e < E) {
        int d = dst[e];
        atomicAdd(&g_deg[d], w[e]);
        atomicAdd(&g_cnt[d], 1);
    }
}

__global__ void dinv_kernel(int n) {
    int i = blockIdx.x * blockDim.x + threadIdx.x;
    if (i < n) g_dinv[i] = rsqrtf(g_deg[i] + 1.0f);  // +1 = self loop weight
}

// ---------------- W convert kernels: fp32 [k][n] -> fp16 transposed [n][k] ---
__global__ void convw1_kernel(const float* __restrict__ W,
                              __half* __restrict__ Wt) {
    int i = blockIdx.x * blockDim.x + threadIdx.x;  // i = n*128 + k
    if (i < 128 * 128) {
        int nn = i >> 7, kk = i & 127;
        Wt[i] = __float2half_rn(W[kk * 128 + nn]);
    }
}
__global__ void convw2_kernel(const float* __restrict__ W,
                              __half* __restrict__ Wt) {
    int i = blockIdx.x * blockDim.x + threadIdx.x;  // i = n*128 + k
    if (i < 64 * 128) {
        int nn = i >> 7, kk = i & 127;
        Wt[i] = __float2half_rn(W[kk * 64 + nn]);
    }
}

// ---------------- hierarchical scan ----------------
__global__ void scan_local_kernel(int n) {
    __shared__ int warp_sums[32];
    int tid  = threadIdx.x;
    int i    = blockIdx.x * SCAN_B + tid;
    int lane = tid & 31;
    int wid  = tid >> 5;

    int v = (i < n) ? g_cnt[i] : 0;

    int s = v;
    #pragma unroll
    for (int off = 1; off < 32; off <<= 1) {
        int t = __shfl_up_sync(0xffffffffu, s, off);
        if (lane >= off) s += t;
    }
    if (lane == 31) warp_sums[wid] = s;
    __syncthreads();

    if (wid == 0) {
        int ws = warp_sums[lane];
        int sw = ws;
        #pragma unroll
        for (int off = 1; off < 32; off <<= 1) {
            int t = __shfl_up_sync(0xffffffffu, sw, off);
            if (lane >= off) sw += t;
        }
        warp_sums[lane] = sw - ws;  // exclusive
        if (lane == 31 && blockIdx.x < NBLK) g_blksum[blockIdx.x] = sw;
    }
    __syncthreads();

    int excl = s - v + warp_sums[wid];
    if (i < n) g_rowptr[i] = excl;
}

__global__ void scan_blocks_kernel(int n) {
    __shared__ int sh[128];
    int tid = threadIdx.x;  // 128 threads
    int v = (tid < NBLK) ? g_blksum[tid] : 0;
    sh[tid] = v;
    __syncthreads();
    #pragma unroll
    for (int off = 1; off < 128; off <<= 1) {
        int t = (tid >= off) ? sh[tid - off] : 0;
        __syncthreads();
        sh[tid] += t;
        __syncthreads();
    }
    if (tid < NBLK) g_blkoff[tid] = sh[tid] - v;
    if (tid == 127) g_rowptr[n] = sh[127];
}

__global__ void scan_apply_kernel(int n) {
    int i = blockIdx.x * blockDim.x + threadIdx.x;
    if (i < n) {
        int r = g_rowptr[i] + g_blkoff[i >> 10];
        g_rowptr[i] = r;
        g_fill[i]   = r;
    }
}

// ---------------- scatter edges into CSR order (packed 8B) ----------------
__global__ void scatter_kernel(const int* __restrict__ src,
                               const int* __restrict__ dst,
                               const float* __restrict__ w, int E) {
    int e = blockIdx.x * blockDim.x + threadIdx.x;
    if (e < E) {
        int d = dst[e];
        int s = src[e];
        int pos = atomicAdd(&g_fill[d], 1);
        float nm = g_dinv[s] * w[e];
        unsigned long long pk =
            (unsigned long long)(uint32_t)s |
            ((unsigned long long)__float_as_uint(nm) << 32);
        g_edge_p[pos] = pk;
    }
}

// ---------------- GEMM1: C[n,128](fp16) = A[n,128](fp32) @ W1h^T (HMMA) -----
// A converted fp32->fp16 during smem load. B = W1 fp16 transposed [n][k].
__global__ void __launch_bounds__(256, 2)
gemm1_kernel(const float* __restrict__ A,
             const __half* __restrict__ Bt,   // [128][128] = [n][k]
             __half* __restrict__ C, int n) {
    constexpr int KC = 32;
    constexpr int LDS_K = KC + 8;   // 40 halves = 80 bytes (16B-aligned stride)
    __shared__ __half As[128][LDS_K];
    __shared__ __half Bs[128][LDS_K];

    int tid  = threadIdx.x;
    int wid  = tid >> 5, lane = tid & 31;
    int wm   = wid >> 2, wn = wid & 3;     // 2 x 4 warps
    int g    = lane >> 2, tg = lane & 3;
    int row0 = blockIdx.x * 128;

    float acc[4][4][4];   // MT=4 m16 tiles, NT=4 n8 tiles
    #pragma unroll
    for (int mi = 0; mi < 4; mi++)
        #pragma unroll
        for (int ni = 0; ni < 4; ni++)
            #pragma unroll
            for (int q = 0; q < 4; q++) acc[mi][ni][q] = 0.f;

    for (int kc = 0; kc < 128; kc += KC) {
        // A chunk: 128 rows x 32 k, fp32 -> fp16
        {
            int r  = tid >> 1;     // 0..127
            int hf = tid & 1;      // 0..1 -> k-halves of 16
            int grow = row0 + r;
            #pragma unroll
            for (int j = 0; j < 4; j++) {
                float4 v = make_float4(0.f, 0.f, 0.f, 0.f);
                if (grow < n)
                    v = *(const float4*)&A[(size_t)grow * 128 + kc + hf * 16 + j * 4];
                __half2 h0 = __floats2half2_rn(v.x, v.y);
                __half2 h1 = __floats2half2_rn(v.z, v.w);
                uint2 pk;
                pk.x = *reinterpret_cast<uint32_t*>(&h0);
                pk.y = *reinterpret_cast<uint32_t*>(&h1);
                *(uint2*)&As[r][hf * 16 + j * 4] = pk;
            }
        }
        // B chunk: 128 n x 32 k fp16 (already transposed in global)
        {
            #pragma unroll
            for (int i = tid; i < 128 * 4; i += 256) {
                int nn = i >> 2, q = i & 3;
                uint4 v = *(const uint4*)&Bt[(size_t)nn * 128 + kc + q * 8];
                *(uint4*)&Bs[nn][q * 8] = v;
            }
        }
        __syncthreads();
        #pragma unroll
        for (int ks = 0; ks < KC; ks += 16) {
            uint32_t a[4][4];
            #pragma unroll
            for (int mi = 0; mi < 4; mi++) {
                int br = wm * 64 + mi * 16;
                a[mi][0] = *(uint32_t*)&As[br + g    ][ks + tg * 2    ];
                a[mi][1] = *(uint32_t*)&As[br + g + 8][ks + tg * 2    ];
                a[mi][2] = *(uint32_t*)&As[br + g    ][ks + tg * 2 + 8];
                a[mi][3] = *(uint32_t*)&As[br + g + 8][ks + tg * 2 + 8];
            }
            #pragma unroll
            for (int ni = 0; ni < 4; ni++) {
                int col = wn * 32 + ni * 8 + g;
                uint32_t b0 = *(uint32_t*)&Bs[col][ks + tg * 2    ];
                uint32_t b1 = *(uint32_t*)&Bs[col][ks + tg * 2 + 8];
                #pragma unroll
                for (int mi = 0; mi < 4; mi++)
                    MMA_F16(acc[mi][ni], a[mi], b0, b1);
            }
        }
        __syncthreads();
    }
    #pragma unroll
    for (int mi = 0; mi < 4; mi++) {
        #pragma unroll
        for (int ni = 0; ni < 4; ni++) {
            int row = row0 + wm * 64 + mi * 16 + g;
            int col = wn * 32 + ni * 8 + tg * 2;
            if (row < n) {
                __half2 v0 = __floats2half2_rn(acc[mi][ni][0], acc[mi][ni][1]);
                *(__half2*)&C[(size_t)row * 128 + col] = v0;
            }
            if (row + 8 < n) {
                __half2 v1 = __floats2half2_rn(acc[mi][ni][2], acc[mi][ni][3]);
                *(__half2*)&C[(size_t)(row + 8) * 128 + col] = v1;
            }
        }
    }
}

// ---------------- GEMM2: C[n,64](fp16) = A[n,128](fp16) @ W2h^T (HMMA) ------
__global__ void __launch_bounds__(256, 2)
gemm2_kernel(const __half* __restrict__ A,
             const __half* __restrict__ Bt,   // [64][128] = [n][k]
             __half* __restrict__ C, int n) {
    constexpr int KC = 32;
    constexpr int LDS_K = KC + 8;
    __shared__ __half As[128][LDS_K];
    __shared__ __half Bs[64][LDS_K];

    int tid  = threadIdx.x;
    int wid  = tid >> 5, lane = tid & 31;
    int wm   = wid >> 1, wn = wid & 1;     // 4 x 2 warps
    int g    = lane >> 2, tg = lane & 3;
    int row0 = blockIdx.x * 128;

    float acc[2][4][4];   // MT=2, NT=4
    #pragma unroll
    for (int mi = 0; mi < 2; mi++)
        #pragma unroll
        for (int ni = 0; ni < 4; ni++)
            #pragma unroll
            for (int q = 0; q < 4; q++) acc[mi][ni][q] = 0.f;

    for (int kc = 0; kc < 128; kc += KC) {
        // A chunk: 128 rows x 32 k fp16
        {
            int r  = tid >> 1;
            int hf = tid & 1;
            int grow = row0 + r;
            #pragma unroll
            for (int j = 0; j < 2; j++) {
                uint4 v = make_uint4(0, 0, 0, 0);
                if (grow < n)
                    v = *(const uint4*)&A[(size_t)grow * 128 + kc + hf * 16 + j * 8];
                *(uint4*)&As[r][hf * 16 + j * 8] = v;
            }
        }
        // B chunk: 64 n x 32 k fp16
        {
            int i = tid;   // 64*4 = 256 loads
            int nn = i >> 2, q = i & 3;
            uint4 v = *(const uint4*)&Bt[(size_t)nn * 128 + kc + q * 8];
            *(uint4*)&Bs[nn][q * 8] = v;
        }
        __syncthreads();
        #pragma unroll
        for (int ks = 0; ks < KC; ks += 16) {
            uint32_t a[2][4];
            #pragma unroll
            for (int mi = 0; mi < 2; mi++) {
                int br = wm * 32 + mi * 16;
                a[mi][0] = *(uint32_t*)&As[br + g    ][ks + tg * 2    ];
                a[mi][1] = *(uint32_t*)&As[br + g + 8][ks + tg * 2    ];
                a[mi][2] = *(uint32_t*)&As[br + g    ][ks + tg * 2 + 8];
                a[mi][3] = *(uint32_t*)&As[br + g + 8][ks + tg * 2 + 8];
            }
            #pragma unroll
            for (int ni = 0; ni < 4; ni++) {
                int col = wn * 32 + ni * 8 + g;
                uint32_t b0 = *(uint32_t*)&Bs[col][ks + tg * 2    ];
                uint32_t b1 = *(uint32_t*)&Bs[col][ks + tg * 2 + 8];
                #pragma unroll
                for (int mi = 0; mi < 2; mi++)
                    MMA_F16(acc[mi][ni], a[mi], b0, b1);
            }
        }
        __syncthreads();
    }
    #pragma unroll
    for (int mi = 0; mi < 2; mi++) {
        #pragma unroll
        for (int ni = 0; ni < 4; ni++) {
            int row = row0 + wm * 32 + mi * 16 + g;
            int col = wn * 32 + ni * 8 + tg * 2;
            if (row < n) {
                __half2 v0 = __floats2half2_rn(acc[mi][ni][0], acc[mi][ni][1]);
                *(__half2*)&C[(size_t)row * 64 + col] = v0;
            }
            if (row + 8 < n) {
                __half2 v1 = __floats2half2_rn(acc[mi][ni][2], acc[mi][ni][3]);
                *(__half2*)&C[(size_t)(row + 8) * 64 + col] = v1;
            }
        }
    }
}

// ---------------- CSR aggregation (fp16 rows): one warp per node ------------
__device__ __forceinline__ void gather_row128(const __half* __restrict__ h,
                                              int s, int lane, float nm,
                                              float acc[4]) {
    uint2 rv = *(const uint2*)&h[(size_t)s * 128 + lane * 4];
    __half2 p0 = *reinterpret_cast<__half2*>(&rv.x);
    __half2 p1 = *reinterpret_cast<__half2*>(&rv.y);
    float2 f0 = __half22float2(p0);
    float2 f1 = __half22float2(p1);
    acc[0] += nm * f0.x; acc[1] += nm * f0.y;
    acc[2] += nm * f1.x; acc[3] += nm * f1.y;
}

__global__ void agg1_kernel(const float* __restrict__ bias, int n) {
    int gwarp = (blockIdx.x * blockDim.x + threadIdx.x) >> 5;
    int lane  = threadIdx.x & 31;
    if (gwarp >= n) return;
    int node = gwarp;

    float dv = g_dinv[node];
    float acc[4] = {0.f, 0.f, 0.f, 0.f};

    int beg = g_rowptr[node];
    int end = g_rowptr[node + 1];
    int e = beg;
    for (; e + 1 < end; e += 2) {
        unsigned long long p0 = g_edge_p[e];
        unsigned long long p1 = g_edge_p[e + 1];
        int   s0 = (int)(uint32_t)p0;
        int   s1 = (int)(uint32_t)p1;
        float n0 = __uint_as_float((uint32_t)(p0 >> 32)) * dv;
        float n1 = __uint_as_float((uint32_t)(p1 >> 32)) * dv;
        gather_row128(g_h1, s0, lane, n0, acc);
        gather_row128(g_h1, s1, lane, n1, acc);
    }
    if (e < end) {
        unsigned long long p0 = g_edge_p[e];
        int   s0 = (int)(uint32_t)p0;
        float n0 = __uint_as_float((uint32_t)(p0 >> 32)) * dv;
        gather_row128(g_h1, s0, lane, n0, acc);
    }
    gather_row128(g_h1, node, lane, dv * dv, acc);   // self loop

    float r0 = fmaxf(acc[0] + bias[lane*4+0], 0.f);
    float r1 = fmaxf(acc[1] + bias[lane*4+1], 0.f);
    float r2 = fmaxf(acc[2] + bias[lane*4+2], 0.f);
    float r3 = fmaxf(acc[3] + bias[lane*4+3], 0.f);
    uint2 ov;
    __half2 o0 = __floats2half2_rn(r0, r1);
    __half2 o1 = __floats2half2_rn(r2, r3);
    ov.x = *reinterpret_cast<uint32_t*>(&o0);
    ov.y = *reinterpret_cast<uint32_t*>(&o1);
    *(uint2*)&g_a1[(size_t)node * 128 + lane * 4] = ov;
}

__device__ __forceinline__ void gather_row64(const __half* __restrict__ h,
                                             int s, int lane, float nm,
                                             float acc[2]) {
    uint32_t rv = *(const uint32_t*)&h[(size_t)s * 64 + lane * 2];
    __half2 p0 = *reinterpret_cast<__half2*>(&rv);
    float2 f0 = __half22float2(p0);
    acc[0] += nm * f0.x; acc[1] += nm * f0.y;
}

__global__ void agg2_kernel(const float* __restrict__ bias,
                            float* __restrict__ out, int n) {
    int gwarp = (blockIdx.x * blockDim.x + threadIdx.x) >> 5;
    int lane  = threadIdx.x & 31;
    if (gwarp >= n) return;
    int node = gwarp;

    float dv = g_dinv[node];
    float acc[2] = {0.f, 0.f};

    int beg = g_rowptr[node];
    int end = g_rowptr[node + 1];
    int e = beg;
    for (; e + 1 < end; e += 2) {
        unsigned long long p0 = g_edge_p[e];
        unsigned long long p1 = g_edge_p[e + 1];
        int   s0 = (int)(uint32_t)p0;
        int   s1 = (int)(uint32_t)p1;
        float n0 = __uint_as_float((uint32_t)(p0 >> 32)) * dv;
        float n1 = __uint_as_float((uint32_t)(p1 >> 32)) * dv;
        gather_row64(g_h2, s0, lane, n0, acc);
        gather_row64(g_h2, s1, lane, n1, acc);
    }
    if (e < end) {
        unsigned long long p0 = g_edge_p[e];
        int   s0 = (int)(uint32_t)p0;
        float n0 = __uint_as_float((uint32_t)(p0 >> 32)) * dv;
        gather_row64(g_h2, s0, lane, n0, acc);
    }
    gather_row64(g_h2, node, lane, dv * dv, acc);   // self loop

    float2 r;
    r.x = acc[0] + bias[lane*2+0];
    r.y = acc[1] + bias[lane*2+1];
    *(float2*)&out[(size_t)node * 64 + lane * 2] = r;
}

// ---------------- launch ----------------
extern "C" void kernel_launch(void* const* d_in, const int* in_sizes, int n_in,
                              void* d_out, int out_size) {
    const float* x  = (const float*)d_in[0];
    const int*   ei = (const int*)  d_in[1];
    const float* w  = (const float*)d_in[2];
    const float* W1 = (const float*)d_in[3];
    const float* b1 = (const float*)d_in[4];
    const float* W2 = (const float*)d_in[5];
    const float* b2 = (const float*)d_in[6];
    float* out = (float*)d_out;

    int E = in_sizes[1] / 2;
    int n = in_sizes[0] / 128;
    const int* src = ei;
    const int* dst = ei + E;

    int nb_n = (n + 255) / 256;
    int nb_e = (E + 255) / 256;
    int nb_s = (n + SCAN_B - 1) / SCAN_B;

    // device addresses of __device__ symbols used as kernel args
    __half* W1h; cudaGetSymbolAddress((void**)&W1h, g_W1h);
    __half* W2h; cudaGetSymbolAddress((void**)&W2h, g_W2h);
    __half* h1;  cudaGetSymbolAddress((void**)&h1,  g_h1);
    __half* a1;  cudaGetSymbolAddress((void**)&a1,  g_a1);
    __half* h2;  cudaGetSymbolAddress((void**)&h2,  g_h2);

    int nb_g = (n + 127) / 128;
    int nb_a = (n + 7) / 8;   // 8 warps per block, 1 warp per node

    // gemm1 stays 4th so ncu profiles it
    convw1_kernel<<<64, 256>>>(W1, W1h);                      // 1
    convw2_kernel<<<32, 256>>>(W2, W2h);                      // 2
    zero_kernel<<<nb_n, 256>>>(n);                            // 3
    gemm1_kernel<<<nb_g, 256>>>(x, W1h, h1, n);               // 4  <- profiled
    deg_hist_kernel<<<nb_e, 256>>>(dst, w, E);                // 5
    dinv_kernel<<<nb_n, 256>>>(n);                            // 6
    scan_local_kernel<<<nb_s, SCAN_B>>>(n);                   // 7
    scan_blocks_kernel<<<1, 128>>>(n);                        // 8
    scan_apply_kernel<<<nb_n, 256>>>(n);                      // 9
    scatter_kernel<<<nb_e, 256>>>(src, dst, w, E);            // 10
    agg1_kernel<<<nb_a, 256>>>(b1, n);                        // 11
    gemm2_kernel<<<nb_g, 256>>>(a1, W2h, h2, n);              // 12
    agg2_kernel<<<nb_a, 256>>>(b2, out, n);                   // 13
}

// round 8
// speedup vs baseline: 1.6719x; 1.0295x over previous
#include <cuda_runtime.h>
#include <cuda_fp16.h>
#include <cstdint>

#define NN 100000
#define EE 1600000
#define SCAN_B 1024
#define NBLK ((NN + SCAN_B - 1) / SCAN_B)   // 98

// ---------------- scratch (static device arrays; no allocation) ----------------
__device__ float g_deg[NN];
__device__ float g_dinv[NN];
__device__ int   g_cnt[NN];
__device__ int   g_rowptr[NN + 1];
__device__ int   g_fill[NN];
__device__ int   g_blksum[NBLK];
__device__ int   g_blkoff[NBLK + 1];
__device__ unsigned long long g_edge_p[EE];  // packed (src, dinv[src]*w) CSR(dst) order
__device__ __half g_h1[(size_t)NN * 128];
__device__ __half g_a1[(size_t)NN * 128];
__device__ __half g_h2[(size_t)NN * 64];
__device__ __half g_W1h[128 * 128];   // W1 transposed [n][k], fp16
__device__ __half g_W2h[64 * 128];    // W2 transposed [n][k], fp16

// ---------------- fp16 HMMA macro (m16n8k16, fp32 accum) ----------------
#define MMA_F16(c, a, b0, b1)                                             \
    asm volatile("mma.sync.aligned.m16n8k16.row.col.f32.f16.f16.f32 "     \
        "{%0,%1,%2,%3}, {%4,%5,%6,%7}, {%8,%9}, {%0,%1,%2,%3};"           \
        : "+f"(c[0]), "+f"(c[1]), "+f"(c[2]), "+f"(c[3])                  \
        : "r"(a[0]), "r"(a[1]), "r"(a[2]), "r"(a[3]), "r"(b0), "r"(b1))

// ---------------- fused W convert: W1 and W2 -> fp16 transposed [n][k] -------
__global__ void convw_kernel(const float* __restrict__ W1,
                             const float* __restrict__ W2,
                             __half* __restrict__ W1t,
                             __half* __restrict__ W2t) {
    int i = blockIdx.x * blockDim.x + threadIdx.x;
    if (i < 128 * 128) {
        int nn = i >> 7, kk = i & 127;
        W1t[i] = __float2half_rn(W1[kk * 128 + nn]);
    } else if (i < 128 * 128 + 64 * 128) {
        int j = i - 128 * 128;
        int nn = j >> 7, kk = j & 127;
        W2t[j] = __float2half_rn(W2[kk * 64 + nn]);
    }
}

__global__ void zero_kernel(int n) {
    int i = blockIdx.x * blockDim.x + threadIdx.x;
    if (i < n) { g_deg[i] = 0.0f; g_cnt[i] = 0; }
}

__global__ void deg_hist_kernel(const int* __restrict__ dst,
                                const float* __restrict__ w, int E) {
    int e = blockIdx.x * blockDim.x + threadIdx.x;
    if (e < E) {
        int d = dst[e];
        atomicAdd(&g_deg[d], w[e]);
        atomicAdd(&g_cnt[d], 1);
    }
}

// ---------------- scan local pass + dinv (fused; both depend on deg_hist) ----
__global__ void scan_local_kernel(int n) {
    __shared__ int warp_sums[32];
    int tid  = threadIdx.x;
    int i    = blockIdx.x * SCAN_B + tid;
    int lane = tid & 31;
    int wid  = tid >> 5;

    // fused dinv
    if (i < n) g_dinv[i] = rsqrtf(g_deg[i] + 1.0f);  // +1 = self loop weight

    int v = (i < n) ? g_cnt[i] : 0;

    int s = v;
    #pragma unroll
    for (int off = 1; off < 32; off <<= 1) {
        int t = __shfl_up_sync(0xffffffffu, s, off);
        if (lane >= off) s += t;
    }
    if (lane == 31) warp_sums[wid] = s;
    __syncthreads();

    if (wid == 0) {
        int ws = warp_sums[lane];
        int sw = ws;
        #pragma unroll
        for (int off = 1; off < 32; off <<= 1) {
            int t = __shfl_up_sync(0xffffffffu, sw, off);
            if (lane >= off) sw += t;
        }
        warp_sums[lane] = sw - ws;  // exclusive
        if (lane == 31 && blockIdx.x < NBLK) g_blksum[blockIdx.x] = sw;
    }
    __syncthreads();

    int excl = s - v + warp_sums[wid];
    if (i < n) g_rowptr[i] = excl;
}

__global__ void scan_blocks_kernel(int n) {
    __shared__ int sh[128];
    int tid = threadIdx.x;  // 128 threads
    int v = (tid < NBLK) ? g_blksum[tid] : 0;
    sh[tid] = v;
    __syncthreads();
    #pragma unroll
    for (int off = 1; off < 128; off <<= 1) {
        int t = (tid >= off) ? sh[tid - off] : 0;
        __syncthreads();
        sh[tid] += t;
        __syncthreads();
    }
    if (tid < NBLK) g_blkoff[tid] = sh[tid] - v;
    if (tid == 127) g_rowptr[n] = sh[127];
}

__global__ void scan_apply_kernel(int n) {
    int i = blockIdx.x * blockDim.x + threadIdx.x;
    if (i < n) {
        int r = g_rowptr[i] + g_blkoff[i >> 10];
        g_rowptr[i] = r;
        g_fill[i]   = r;
    }
}

// ---------------- scatter edges into CSR order (packed 8B) ----------------
__global__ void scatter_kernel(const int* __restrict__ src,
                               const int* __restrict__ dst,
                               const float* __restrict__ w, int E) {
    int e = blockIdx.x * blockDim.x + threadIdx.x;
    if (e < E) {
        int d = dst[e];
        int s = src[e];
        int pos = atomicAdd(&g_fill[d], 1);
        float nm = g_dinv[s] * w[e];
        unsigned long long pk =
            (unsigned long long)(uint32_t)s |
            ((unsigned long long)__float_as_uint(nm) << 32);
        g_edge_p[pos] = pk;
    }
}

// ---------------- GEMM1: C[n,128](fp16) = A[n,128](fp32) @ W1h^T (HMMA) -----
__global__ void __launch_bounds__(256, 2)
gemm1_kernel(const float* __restrict__ A,
             const __half* __restrict__ Bt,   // [128][128] = [n][k]
             __half* __restrict__ C, int n) {
    constexpr int KC = 32;
    constexpr int LDS_K = KC + 8;   // 40 halves = 80 bytes
    __shared__ __half As[128][LDS_K];
    __shared__ __half Bs[128][LDS_K];

    int tid  = threadIdx.x;
    int wid  = tid >> 5, lane = tid & 31;
    int wm   = wid >> 2, wn = wid & 3;     // 2 x 4 warps
    int g    = lane >> 2, tg = lane & 3;
    int row0 = blockIdx.x * 128;

    float acc[4][4][4];
    #pragma unroll
    for (int mi = 0; mi < 4; mi++)
        #pragma unroll
        for (int ni = 0; ni < 4; ni++)
            #pragma unroll
            for (int q = 0; q < 4; q++) acc[mi][ni][q] = 0.f;

    for (int kc = 0; kc < 128; kc += KC) {
        {
            int r  = tid >> 1;     // 0..127
            int hf = tid & 1;      // 0..1
            int grow = row0 + r;
            #pragma unroll
            for (int j = 0; j < 4; j++) {
                float4 v = make_float4(0.f, 0.f, 0.f, 0.f);
                if (grow < n)
                    v = *(const float4*)&A[(size_t)grow * 128 + kc + hf * 16 + j * 4];
                __half2 h0 = __floats2half2_rn(v.x, v.y);
                __half2 h1 = __floats2half2_rn(v.z, v.w);
                uint2 pk;
                pk.x = *reinterpret_cast<uint32_t*>(&h0);
                pk.y = *reinterpret_cast<uint32_t*>(&h1);
                *(uint2*)&As[r][hf * 16 + j * 4] = pk;
            }
        }
        {
            #pragma unroll
            for (int i = tid; i < 128 * 4; i += 256) {
                int nn = i >> 2, q = i & 3;
                uint4 v = *(const uint4*)&Bt[(size_t)nn * 128 + kc + q * 8];
                *(uint4*)&Bs[nn][q * 8] = v;
            }
        }
        __syncthreads();
        #pragma unroll
        for (int ks = 0; ks < KC; ks += 16) {
            uint32_t a[4][4];
            #pragma unroll
            for (int mi = 0; mi < 4; mi++) {
                int br = wm * 64 + mi * 16;
                a[mi][0] = *(uint32_t*)&As[br + g    ][ks + tg * 2    ];
                a[mi][1] = *(uint32_t*)&As[br + g + 8][ks + tg * 2    ];
                a[mi][2] = *(uint32_t*)&As[br + g    ][ks + tg * 2 + 8];
                a[mi][3] = *(uint32_t*)&As[br + g + 8][ks + tg * 2 + 8];
            }
            #pragma unroll
            for (int ni = 0; ni < 4; ni++) {
                int col = wn * 32 + ni * 8 + g;
                uint32_t b0 = *(uint32_t*)&Bs[col][ks + tg * 2    ];
                uint32_t b1 = *(uint32_t*)&Bs[col][ks + tg * 2 + 8];
                #pragma unroll
                for (int mi = 0; mi < 4; mi++)
                    MMA_F16(acc[mi][ni], a[mi], b0, b1);
            }
        }
        __syncthreads();
    }
    #pragma unroll
    for (int mi = 0; mi < 4; mi++) {
        #pragma unroll
        for (int ni = 0; ni < 4; ni++) {
            int row = row0 + wm * 64 + mi * 16 + g;
            int col = wn * 32 + ni * 8 + tg * 2;
            if (row < n) {
                __half2 v0 = __floats2half2_rn(acc[mi][ni][0], acc[mi][ni][1]);
                *(__half2*)&C[(size_t)row * 128 + col] = v0;
            }
            if (row + 8 < n) {
                __half2 v1 = __floats2half2_rn(acc[mi][ni][2], acc[mi][ni][3]);
                *(__half2*)&C[(size_t)(row + 8) * 128 + col] = v1;
            }
        }
    }
}

// ---------------- GEMM2: C[n,64](fp16) = A[n,128](fp16) @ W2h^T (HMMA) ------
__global__ void __launch_bounds__(256, 2)
gemm2_kernel(const __half* __restrict__ A,
             const __half* __restrict__ Bt,   // [64][128]
             __half* __restrict__ C, int n) {
    constexpr int KC = 32;
    constexpr int LDS_K = KC + 8;
    __shared__ __half As[128][LDS_K];
    __shared__ __half Bs[64][LDS_K];

    int tid  = threadIdx.x;
    int wid  = tid >> 5, lane = tid & 31;
    int wm   = wid >> 1, wn = wid & 1;     // 4 x 2 warps
    int g    = lane >> 2, tg = lane & 3;
    int row0 = blockIdx.x * 128;

    float acc[2][4][4];
    #pragma unroll
    for (int mi = 0; mi < 2; mi++)
        #pragma unroll
        for (int ni = 0; ni < 4; ni++)
            #pragma unroll
            for (int q = 0; q < 4; q++) acc[mi][ni][q] = 0.f;

    for (int kc = 0; kc < 128; kc += KC) {
        {
            int r  = tid >> 1;
            int hf = tid & 1;
            int grow = row0 + r;
            #pragma unroll
            for (int j = 0; j < 2; j++) {
                uint4 v = make_uint4(0, 0, 0, 0);
                if (grow < n)
                    v = *(const uint4*)&A[(size_t)grow * 128 + kc + hf * 16 + j * 8];
                *(uint4*)&As[r][hf * 16 + j * 8] = v;
            }
        }
        {
            int i = tid;
            int nn = i >> 2, q = i & 3;
            uint4 v = *(const uint4*)&Bt[(size_t)nn * 128 + kc + q * 8];
            *(uint4*)&Bs[nn][q * 8] = v;
        }
        __syncthreads();
        #pragma unroll
        for (int ks = 0; ks < KC; ks += 16) {
            uint32_t a[2][4];
            #pragma unroll
            for (int mi = 0; mi < 2; mi++) {
                int br = wm * 32 + mi * 16;
                a[mi][0] = *(uint32_t*)&As[br + g    ][ks + tg * 2    ];
                a[mi][1] = *(uint32_t*)&As[br + g + 8][ks + tg * 2    ];
                a[mi][2] = *(uint32_t*)&As[br + g    ][ks + tg * 2 + 8];
                a[mi][3] = *(uint32_t*)&As[br + g + 8][ks + tg * 2 + 8];
            }
            #pragma unroll
            for (int ni = 0; ni < 4; ni++) {
                int col = wn * 32 + ni * 8 + g;
                uint32_t b0 = *(uint32_t*)&Bs[col][ks + tg * 2    ];
                uint32_t b1 = *(uint32_t*)&Bs[col][ks + tg * 2 + 8];
                #pragma unroll
                for (int mi = 0; mi < 2; mi++)
                    MMA_F16(acc[mi][ni], a[mi], b0, b1);
            }
        }
        __syncthreads();
    }
    #pragma unroll
    for (int mi = 0; mi < 2; mi++) {
        #pragma unroll
        for (int ni = 0; ni < 4; ni++) {
            int row = row0 + wm * 32 + mi * 16 + g;
            int col = wn * 32 + ni * 8 + tg * 2;
            if (row < n) {
                __half2 v0 = __floats2half2_rn(acc[mi][ni][0], acc[mi][ni][1]);
                *(__half2*)&C[(size_t)row * 64 + col] = v0;
            }
            if (row + 8 < n) {
                __half2 v1 = __floats2half2_rn(acc[mi][ni][2], acc[mi][ni][3]);
                *(__half2*)&C[(size_t)(row + 8) * 64 + col] = v1;
            }
        }
    }
}

// ---------------- CSR aggregation (fp16 rows): one warp per node ------------
__device__ __forceinline__ void gather_row128(const __half* __restrict__ h,
                                              int s, int lane, float nm,
                                              float acc[4]) {
    uint2 rv = *(const uint2*)&h[(size_t)s * 128 + lane * 4];
    __half2 p0 = *reinterpret_cast<__half2*>(&rv.x);
    __half2 p1 = *reinterpret_cast<__half2*>(&rv.y);
    float2 f0 = __half22float2(p0);
    float2 f1 = __half22float2(p1);
    acc[0] += nm * f0.x; acc[1] += nm * f0.y;
    acc[2] += nm * f1.x; acc[3] += nm * f1.y;
}

__global__ void agg1_kernel(const float* __restrict__ bias, int n) {
    int gwarp = (blockIdx.x * blockDim.x + threadIdx.x) >> 5;
    int lane  = threadIdx.x & 31;
    if (gwarp >= n) return;
    int node = gwarp;

    float dv = g_dinv[node];
    float acc[4] = {0.f, 0.f, 0.f, 0.f};

    int beg = g_rowptr[node];
    int end = g_rowptr[node + 1];
    int e = beg;
    // 4x unroll: 4 independent gathers in flight
    for (; e + 3 < end; e += 4) {
        unsigned long long p0 = g_edge_p[e];
        unsigned long long p1 = g_edge_p[e + 1];
        unsigned long long p2 = g_edge_p[e + 2];
        unsigned long long p3 = g_edge_p[e + 3];
        int   s0 = (int)(uint32_t)p0, s1 = (int)(uint32_t)p1;
        int   s2 = (int)(uint32_t)p2, s3 = (int)(uint32_t)p3;
        float n0 = __uint_as_float((uint32_t)(p0 >> 32)) * dv;
        float n1 = __uint_as_float((uint32_t)(p1 >> 32)) * dv;
        float n2 = __uint_as_float((uint32_t)(p2 >> 32)) * dv;
        float n3 = __uint_as_float((uint32_t)(p3 >> 32)) * dv;
        gather_row128(g_h1, s0, lane, n0, acc);
        gather_row128(g_h1, s1, lane, n1, acc);
        gather_row128(g_h1, s2, lane, n2, acc);
        gather_row128(g_h1, s3, lane, n3, acc);
    }
    for (; e < end; e++) {
        unsigned long long p0 = g_edge_p[e];
        int   s0 = (int)(uint32_t)p0;
        float n0 = __uint_as_float((uint32_t)(p0 >> 32)) * dv;
        gather_row128(g_h1, s0, lane, n0, acc);
    }
    gather_row128(g_h1, node, lane, dv * dv, acc);   // self loop

    float r0 = fmaxf(acc[0] + bias[lane*4+0], 0.f);
    float r1 = fmaxf(acc[1] + bias[lane*4+1], 0.f);
    float r2 = fmaxf(acc[2] + bias[lane*4+2], 0.f);
    float r3 = fmaxf(acc[3] + bias[lane*4+3], 0.f);
    uint2 ov;
    __half2 o0 = __floats2half2_rn(r0, r1);
    __half2 o1 = __floats2half2_rn(r2, r3);
    ov.x = *reinterpret_cast<uint32_t*>(&o0);
    ov.y = *reinterpret_cast<uint32_t*>(&o1);
    *(uint2*)&g_a1[(size_t)node * 128 + lane * 4] = ov;
}

__device__ __forceinline__ void gather_row64(const __half* __restrict__ h,
                                             int s, int lane, float nm,
                                             float acc[2]) {
    uint32_t rv = *(const uint32_t*)&h[(size_t)s * 64 + lane * 2];
    __half2 p0 = *reinterpret_cast<__half2*>(&rv);
    float2 f0 = __half22float2(p0);
    acc[0] += nm * f0.x; acc[1] += nm * f0.y;
}

__global__ void agg2_kernel(const float* __restrict__ bias,
                            float* __restrict__ out, int n) {
    int gwarp = (blockIdx.x * blockDim.x + threadIdx.x) >> 5;
    int lane  = threadIdx.x & 31;
    if (gwarp >= n) return;
    int node = gwarp;

    float dv = g_dinv[node];
    float acc[2] = {0.f, 0.f};

    int beg = g_rowptr[node];
    int end = g_rowptr[node + 1];
    int e = beg;
    for (; e + 3 < end; e += 4) {
        unsigned long long p0 = g_edge_p[e];
        unsigned long long p1 = g_edge_p[e + 1];
        unsigned long long p2 = g_edge_p[e + 2];
        unsigned long long p3 = g_edge_p[e + 3];
        int   s0 = (int)(uint32_t)p0, s1 = (int)(uint32_t)p1;
        int   s2 = (int)(uint32_t)p2, s3 = (int)(uint32_t)p3;
        float n0 = __uint_as_float((uint32_t)(p0 >> 32)) * dv;
        float n1 = __uint_as_float((uint32_t)(p1 >> 32)) * dv;
        float n2 = __uint_as_float((uint32_t)(p2 >> 32)) * dv;
        float n3 = __uint_as_float((uint32_t)(p3 >> 32)) * dv;
        gather_row64(g_h2, s0, lane, n0, acc);
        gather_row64(g_h2, s1, lane, n1, acc);
        gather_row64(g_h2, s2, lane, n2, acc);
        gather_row64(g_h2, s3, lane, n3, acc);
    }
    for (; e < end; e++) {
        unsigned long long p0 = g_edge_p[e];
        int   s0 = (int)(uint32_t)p0;
        float n0 = __uint_as_float((uint32_t)(p0 >> 32)) * dv;
        gather_row64(g_h2, s0, lane, n0, acc);
    }
    gather_row64(g_h2, node, lane, dv * dv, acc);   // self loop

    float2 r;
    r.x = acc[0] + bias[lane*2+0];
    r.y = acc[1] + bias[lane*2+1];
    *(float2*)&out[(size_t)node * 64 + lane * 2] = r;
}

// ---------------- launch ----------------
extern "C" void kernel_launch(void* const* d_in, const int* in_sizes, int n_in,
                              void* d_out, int out_size) {
    const float* x  = (const float*)d_in[0];
    const int*   ei = (const int*)  d_in[1];
    const float* w  = (const float*)d_in[2];
    const float* W1 = (const float*)d_in[3];
    const float* b1 = (const float*)d_in[4];
    const float* W2 = (const float*)d_in[5];
    const float* b2 = (const float*)d_in[6];
    float* out = (float*)d_out;

    int E = in_sizes[1] / 2;
    int n = in_sizes[0] / 128;
    const int* src = ei;
    const int* dst = ei + E;

    int nb_n = (n + 255) / 256;
    int nb_e = (E + 255) / 256;
    int nb_s = (n + SCAN_B - 1) / SCAN_B;

    __half* W1h; cudaGetSymbolAddress((void**)&W1h, g_W1h);
    __half* W2h; cudaGetSymbolAddress((void**)&W2h, g_W2h);
    __half* h1;  cudaGetSymbolAddress((void**)&h1,  g_h1);
    __half* a1;  cudaGetSymbolAddress((void**)&a1,  g_a1);
    __half* h2;  cudaGetSymbolAddress((void**)&h2,  g_h2);

    int nb_g = (n + 127) / 128;
    int nb_a = (n + 7) / 8;

    convw_kernel<<<96, 256>>>(W1, W2, W1h, W2h);              // 1
    zero_kernel<<<nb_n, 256>>>(n);                            // 2
    gemm1_kernel<<<nb_g, 256>>>(x, W1h, h1, n);               // 3
    deg_hist_kernel<<<nb_e, 256>>>(dst, w, E);                // 4  <- profiled
    scan_local_kernel<<<nb_s, SCAN_B>>>(n);                   // 5  (fused dinv)
    scan_blocks_kernel<<<1, 128>>>(n);                        // 6
    scan_apply_kernel<<<nb_n, 256>>>(n);                      // 7
    scatter_kernel<<<nb_e, 256>>>(src, dst, w, E);            // 8
    agg1_kernel<<<nb_a, 256>>>(b1, n);                        // 9
    gemm2_kernel<<<nb_g, 256>>>(a1, W2h, h2, n);              // 10
    agg2_kernel<<<nb_a, 256>>>(b2, out, n);                   // 11
}

// round 9
// speedup vs baseline: 1.8016x; 1.0776x over previous
#include <cuda_runtime.h>
#include <cuda_fp16.h>
#include <cstdint>

#define NN 100000
#define EE 1600000
#define SCAN_B 1024
#define NBLK ((NN + SCAN_B - 1) / SCAN_B)   // 98

// ---------------- scratch (static device arrays; no allocation) ----------------
__device__ unsigned long long g_hist[NN];  // (cnt << 50) | sum(w * 2^32)
__device__ float g_dinv[NN];
__device__ int   g_rowptr[NN + 1];
__device__ int   g_fill[NN];
__device__ int   g_blksum[NBLK];
__device__ int   g_blkoff[NBLK + 1];
__device__ unsigned long long g_edge_p[EE];  // packed (src, dinv[src]*w) CSR(dst) order
__device__ __half g_h1[(size_t)NN * 128];
__device__ __half g_a1[(size_t)NN * 128];
__device__ __half g_h2[(size_t)NN * 64];
__device__ __half g_W1h[128 * 128];   // W1 transposed [n][k], fp16
__device__ __half g_W2h[64 * 128];    // W2 transposed [n][k], fp16

// ---------------- fp16 HMMA macro (m16n8k16, fp32 accum) ----------------
#define MMA_F16(c, a, b0, b1)                                             \
    asm volatile("mma.sync.aligned.m16n8k16.row.col.f32.f16.f16.f32 "     \
        "{%0,%1,%2,%3}, {%4,%5,%6,%7}, {%8,%9}, {%0,%1,%2,%3};"           \
        : "+f"(c[0]), "+f"(c[1]), "+f"(c[2]), "+f"(c[3])                  \
        : "r"(a[0]), "r"(a[1]), "r"(a[2]), "r"(a[3]), "r"(b0), "r"(b1))

// ---------------- fused W convert: W1 and W2 -> fp16 transposed [n][k] -------
__global__ void convw_kernel(const float* __restrict__ W1,
                             const float* __restrict__ W2,
                             __half* __restrict__ W1t,
                             __half* __restrict__ W2t) {
    int i = blockIdx.x * blockDim.x + threadIdx.x;
    if (i < 128 * 128) {
        int nn = i >> 7, kk = i & 127;
        W1t[i] = __float2half_rn(W1[kk * 128 + nn]);
    } else if (i < 128 * 128 + 64 * 128) {
        int j = i - 128 * 128;
        int nn = j >> 7, kk = j & 127;
        W2t[j] = __float2half_rn(W2[kk * 64 + nn]);
    }
}

__global__ void zero_kernel(int n) {
    int i = blockIdx.x * blockDim.x + threadIdx.x;
    if (i < n) g_hist[i] = 0ULL;
}

// ---------------- merged histogram: ONE u64 atomic per edge ------------------
// packs count at bit 50 and fixed-point(2^-32) weight sum in low 50 bits
__global__ void hist_kernel(const int* __restrict__ dst,
                            const float* __restrict__ w, int E) {
    int e = blockIdx.x * blockDim.x + threadIdx.x;
    if (e < E) {
        int d = dst[e];
        unsigned long long v =
            (1ULL << 50) | (unsigned long long)((double)w[e] * 4294967296.0);
        atomicAdd(&g_hist[d], v);
    }
}

// ---------------- scan local pass + dinv extraction (fused) ------------------
__global__ void scan_local_kernel(int n) {
    __shared__ int warp_sums[32];
    int tid  = threadIdx.x;
    int i    = blockIdx.x * SCAN_B + tid;
    int lane = tid & 31;
    int wid  = tid >> 5;

    unsigned long long hv = (i < n) ? g_hist[i] : 0ULL;
    int v = (int)(hv >> 50);
    if (i < n) {
        float wsum = (float)(hv & ((1ULL << 50) - 1)) * (1.0f / 4294967296.0f);
        g_dinv[i] = rsqrtf(wsum + 1.0f);   // +1 = self loop weight
    }

    int s = v;
    #pragma unroll
    for (int off = 1; off < 32; off <<= 1) {
        int t = __shfl_up_sync(0xffffffffu, s, off);
        if (lane >= off) s += t;
    }
    if (lane == 31) warp_sums[wid] = s;
    __syncthreads();

    if (wid == 0) {
        int ws = warp_sums[lane];
        int sw = ws;
        #pragma unroll
        for (int off = 1; off < 32; off <<= 1) {
            int t = __shfl_up_sync(0xffffffffu, sw, off);
            if (lane >= off) sw += t;
        }
        warp_sums[lane] = sw - ws;  // exclusive
        if (lane == 31 && blockIdx.x < NBLK) g_blksum[blockIdx.x] = sw;
    }
    __syncthreads();

    int excl = s - v + warp_sums[wid];
    if (i < n) g_rowptr[i] = excl;
}

__global__ void scan_blocks_kernel(int n) {
    __shared__ int sh[128];
    int tid = threadIdx.x;  // 128 threads
    int v = (tid < NBLK) ? g_blksum[tid] : 0;
    sh[tid] = v;
    __syncthreads();
    #pragma unroll
    for (int off = 1; off < 128; off <<= 1) {
        int t = (tid >= off) ? sh[tid - off] : 0;
        __syncthreads();
        sh[tid] += t;
        __syncthreads();
    }
    if (tid < NBLK) g_blkoff[tid] = sh[tid] - v;
    if (tid == 127) g_rowptr[n] = sh[127];
}

__global__ void scan_apply_kernel(int n) {
    int i = blockIdx.x * blockDim.x + threadIdx.x;
    if (i < n) {
        int r = g_rowptr[i] + g_blkoff[i >> 10];
        g_rowptr[i] = r;
        g_fill[i]   = r;
    }
}

// ---------------- scatter edges into CSR order (packed 8B) ----------------
__global__ void scatter_kernel(const int* __restrict__ src,
                               const int* __restrict__ dst,
                               const float* __restrict__ w, int E) {
    int e = blockIdx.x * blockDim.x + threadIdx.x;
    if (e < E) {
        int d = dst[e];
        int s = src[e];
        int pos = atomicAdd(&g_fill[d], 1);
        float nm = g_dinv[s] * w[e];
        unsigned long long pk =
            (unsigned long long)(uint32_t)s |
            ((unsigned long long)__float_as_uint(nm) << 32);
        g_edge_p[pos] = pk;
    }
}

// ---------------- GEMM1: C[n,128](fp16) = A[n,128](fp32) @ W1h^T (HMMA) -----
__global__ void __launch_bounds__(256, 2)
gemm1_kernel(const float* __restrict__ A,
             const __half* __restrict__ Bt,   // [128][128] = [n][k]
             __half* __restrict__ C, int n) {
    constexpr int KC = 32;
    constexpr int LDS_K = KC + 8;   // 40 halves = 80 bytes
    __shared__ __half As[128][LDS_K];
    __shared__ __half Bs[128][LDS_K];

    int tid  = threadIdx.x;
    int wid  = tid >> 5, lane = tid & 31;
    int wm   = wid >> 2, wn = wid & 3;     // 2 x 4 warps
    int g    = lane >> 2, tg = lane & 3;
    int row0 = blockIdx.x * 128;

    float acc[4][4][4];
    #pragma unroll
    for (int mi = 0; mi < 4; mi++)
        #pragma unroll
        for (int ni = 0; ni < 4; ni++)
            #pragma unroll
            for (int q = 0; q < 4; q++) acc[mi][ni][q] = 0.f;

    for (int kc = 0; kc < 128; kc += KC) {
        {
            int r  = tid >> 1;     // 0..127
            int hf = tid & 1;      // 0..1
            int grow = row0 + r;
            #pragma unroll
            for (int j = 0; j < 4; j++) {
                float4 v = make_float4(0.f, 0.f, 0.f, 0.f);
                if (grow < n)
                    v = *(const float4*)&A[(size_t)grow * 128 + kc + hf * 16 + j * 4];
                __half2 h0 = __floats2half2_rn(v.x, v.y);
                __half2 h1 = __floats2half2_rn(v.z, v.w);
                uint2 pk;
                pk.x = *reinterpret_cast<uint32_t*>(&h0);
                pk.y = *reinterpret_cast<uint32_t*>(&h1);
                *(uint2*)&As[r][hf * 16 + j * 4] = pk;
            }
        }
        {
            #pragma unroll
            for (int i = tid; i < 128 * 4; i += 256) {
                int nn = i >> 2, q = i & 3;
                uint4 v = *(const uint4*)&Bt[(size_t)nn * 128 + kc + q * 8];
                *(uint4*)&Bs[nn][q * 8] = v;
            }
        }
        __syncthreads();
        #pragma unroll
        for (int ks = 0; ks < KC; ks += 16) {
            uint32_t a[4][4];
            #pragma unroll
            for (int mi = 0; mi < 4; mi++) {
                int br = wm * 64 + mi * 16;
                a[mi][0] = *(uint32_t*)&As[br + g    ][ks + tg * 2    ];
                a[mi][1] = *(uint32_t*)&As[br + g + 8][ks + tg * 2    ];
                a[mi][2] = *(uint32_t*)&As[br + g    ][ks + tg * 2 + 8];
                a[mi][3] = *(uint32_t*)&As[br + g + 8][ks + tg * 2 + 8];
            }
            #pragma unroll
            for (int ni = 0; ni < 4; ni++) {
                int col = wn * 32 + ni * 8 + g;
                uint32_t b0 = *(uint32_t*)&Bs[col][ks + tg * 2    ];
                uint32_t b1 = *(uint32_t*)&Bs[col][ks + tg * 2 + 8];
                #pragma unroll
                for (int mi = 0; mi < 4; mi++)
                    MMA_F16(acc[mi][ni], a[mi], b0, b1);
            }
        }
        __syncthreads();
    }
    #pragma unroll
    for (int mi = 0; mi < 4; mi++) {
        #pragma unroll
        for (int ni = 0; ni < 4; ni++) {
            int row = row0 + wm * 64 + mi * 16 + g;
            int col = wn * 32 + ni * 8 + tg * 2;
            if (row < n) {
                __half2 v0 = __floats2half2_rn(acc[mi][ni][0], acc[mi][ni][1]);
                *(__half2*)&C[(size_t)row * 128 + col] = v0;
            }
            if (row + 8 < n) {
                __half2 v1 = __floats2half2_rn(acc[mi][ni][2], acc[mi][ni][3]);
                *(__half2*)&C[(size_t)(row + 8) * 128 + col] = v1;
            }
        }
    }
}

// ---------------- GEMM2: C[n,64](fp16) = A[n,128](fp16) @ W2h^T (HMMA) ------
__global__ void __launch_bounds__(256, 2)
gemm2_kernel(const __half* __restrict__ A,
             const __half* __restrict__ Bt,   // [64][128]
             __half* __restrict__ C, int n) {
    constexpr int KC = 32;
    constexpr int LDS_K = KC + 8;
    __shared__ __half As[128][LDS_K];
    __shared__ __half Bs[64][LDS_K];

    int tid  = threadIdx.x;
    int wid  = tid >> 5, lane = tid & 31;
    int wm   = wid >> 1, wn = wid & 1;     // 4 x 2 warps
    int g    = lane >> 2, tg = lane & 3;
    int row0 = blockIdx.x * 128;

    float acc[2][4][4];
    #pragma unroll
    for (int mi = 0; mi < 2; mi++)
        #pragma unroll
        for (int ni = 0; ni < 4; ni++)
            #pragma unroll
            for (int q = 0; q < 4; q++) acc[mi][ni][q] = 0.f;

    for (int kc = 0; kc < 128; kc += KC) {
        {
            int r  = tid >> 1;
            int hf = tid & 1;
            int grow = row0 + r;
            #pragma unroll
            for (int j = 0; j < 2; j++) {
                uint4 v = make_uint4(0, 0, 0, 0);
                if (grow < n)
                    v = *(const uint4*)&A[(size_t)grow * 128 + kc + hf * 16 + j * 8];
                *(uint4*)&As[r][hf * 16 + j * 8] = v;
            }
        }
        {
            int i = tid;
            int nn = i >> 2, q = i & 3;
            uint4 v = *(const uint4*)&Bt[(size_t)nn * 128 + kc + q * 8];
            *(uint4*)&Bs[nn][q * 8] = v;
        }
        __syncthreads();
        #pragma unroll
        for (int ks = 0; ks < KC; ks += 16) {
            uint32_t a[2][4];
            #pragma unroll
            for (int mi = 0; mi < 2; mi++) {
                int br = wm * 32 + mi * 16;
                a[mi][0] = *(uint32_t*)&As[br + g    ][ks + tg * 2    ];
                a[mi][1] = *(uint32_t*)&As[br + g + 8][ks + tg * 2    ];
                a[mi][2] = *(uint32_t*)&As[br + g    ][ks + tg * 2 + 8];
                a[mi][3] = *(uint32_t*)&As[br + g + 8][ks + tg * 2 + 8];
            }
            #pragma unroll
            for (int ni = 0; ni < 4; ni++) {
                int col = wn * 32 + ni * 8 + g;
                uint32_t b0 = *(uint32_t*)&Bs[col][ks + tg * 2    ];
                uint32_t b1 = *(uint32_t*)&Bs[col][ks + tg * 2 + 8];
                #pragma unroll
                for (int mi = 0; mi < 2; mi++)
                    MMA_F16(acc[mi][ni], a[mi], b0, b1);
            }
        }
        __syncthreads();
    }
    #pragma unroll
    for (int mi = 0; mi < 2; mi++) {
        #pragma unroll
        for (int ni = 0; ni < 4; ni++) {
            int row = row0 + wm * 32 + mi * 16 + g;
            int col = wn * 32 + ni * 8 + tg * 2;
            if (row < n) {
                __half2 v0 = __floats2half2_rn(acc[mi][ni][0], acc[mi][ni][1]);
                *(__half2*)&C[(size_t)row * 64 + col] = v0;
            }
            if (row + 8 < n) {
                __half2 v1 = __floats2half2_rn(acc[mi][ni][2], acc[mi][ni][3]);
                *(__half2*)&C[(size_t)(row + 8) * 64 + col] = v1;
            }
        }
    }
}

// ---------------- CSR aggregation (fp16 rows): one warp per node ------------
__device__ __forceinline__ void gather_row128(const __half* __restrict__ h,
                                              int s, int lane, float nm,
                                              float acc[4]) {
    uint2 rv = *(const uint2*)&h[(size_t)s * 128 + lane * 4];
    __half2 p0 = *reinterpret_cast<__half2*>(&rv.x);
    __half2 p1 = *reinterpret_cast<__half2*>(&rv.y);
    float2 f0 = __half22float2(p0);
    float2 f1 = __half22float2(p1);
    acc[0] += nm * f0.x; acc[1] += nm * f0.y;
    acc[2] += nm * f1.x; acc[3] += nm * f1.y;
}

__global__ void agg1_kernel(const float* __restrict__ bias, int n) {
    int gwarp = (blockIdx.x * blockDim.x + threadIdx.x) >> 5;
    int lane  = threadIdx.x & 31;
    if (gwarp >= n) return;
    int node = gwarp;

    float dv = g_dinv[node];
    float acc[4] = {0.f, 0.f, 0.f, 0.f};

    int beg = g_rowptr[node];
    int end = g_rowptr[node + 1];
    int e = beg;
    for (; e + 3 < end; e += 4) {
        unsigned long long p0 = g_edge_p[e];
        unsigned long long p1 = g_edge_p[e + 1];
        unsigned long long p2 = g_edge_p[e + 2];
        unsigned long long p3 = g_edge_p[e + 3];
        int   s0 = (int)(uint32_t)p0, s1 = (int)(uint32_t)p1;
        int   s2 = (int)(uint32_t)p2, s3 = (int)(uint32_t)p3;
        float n0 = __uint_as_float((uint32_t)(p0 >> 32)) * dv;
        float n1 = __uint_as_float((uint32_t)(p1 >> 32)) * dv;
        float n2 = __uint_as_float((uint32_t)(p2 >> 32)) * dv;
        float n3 = __uint_as_float((uint32_t)(p3 >> 32)) * dv;
        gather_row128(g_h1, s0, lane, n0, acc);
        gather_row128(g_h1, s1, lane, n1, acc);
        gather_row128(g_h1, s2, lane, n2, acc);
        gather_row128(g_h1, s3, lane, n3, acc);
    }
    for (; e < end; e++) {
        unsigned long long p0 = g_edge_p[e];
        int   s0 = (int)(uint32_t)p0;
        float n0 = __uint_as_float((uint32_t)(p0 >> 32)) * dv;
        gather_row128(g_h1, s0, lane, n0, acc);
    }
    gather_row128(g_h1, node, lane, dv * dv, acc);   // self loop

    float r0 = fmaxf(acc[0] + bias[lane*4+0], 0.f);
    float r1 = fmaxf(acc[1] + bias[lane*4+1], 0.f);
    float r2 = fmaxf(acc[2] + bias[lane*4+2], 0.f);
    float r3 = fmaxf(acc[3] + bias[lane*4+3], 0.f);
    uint2 ov;
    __half2 o0 = __floats2half2_rn(r0, r1);
    __half2 o1 = __floats2half2_rn(r2, r3);
    ov.x = *reinterpret_cast<uint32_t*>(&o0);
    ov.y = *reinterpret_cast<uint32_t*>(&o1);
    *(uint2*)&g_a1[(size_t)node * 128 + lane * 4] = ov;
}

__device__ __forceinline__ void gather_row64(const __half* __restrict__ h,
                                             int s, int lane, float nm,
                                             float acc[2]) {
    uint32_t rv = *(const uint32_t*)&h[(size_t)s * 64 + lane * 2];
    __half2 p0 = *reinterpret_cast<__half2*>(&rv);
    float2 f0 = __half22float2(p0);
    acc[0] += nm * f0.x; acc[1] += nm * f0.y;
}

__global__ void agg2_kernel(const float* __restrict__ bias,
                            float* __restrict__ out, int n) {
    int gwarp = (blockIdx.x * blockDim.x + threadIdx.x) >> 5;
    int lane  = threadIdx.x & 31;
    if (gwarp >= n) return;
    int node = gwarp;

    float dv = g_dinv[node];
    float acc[2] = {0.f, 0.f};

    int beg = g_rowptr[node];
    int end = g_rowptr[node + 1];
    int e = beg;
    for (; e + 3 < end; e += 4) {
        unsigned long long p0 = g_edge_p[e];
        unsigned long long p1 = g_edge_p[e + 1];
        unsigned long long p2 = g_edge_p[e + 2];
        unsigned long long p3 = g_edge_p[e + 3];
        int   s0 = (int)(uint32_t)p0, s1 = (int)(uint32_t)p1;
        int   s2 = (int)(uint32_t)p2, s3 = (int)(uint32_t)p3;
        float n0 = __uint_as_float((uint32_t)(p0 >> 32)) * dv;
        float n1 = __uint_as_float((uint32_t)(p1 >> 32)) * dv;
        float n2 = __uint_as_float((uint32_t)(p2 >> 32)) * dv;
        float n3 = __uint_as_float((uint32_t)(p3 >> 32)) * dv;
        gather_row64(g_h2, s0, lane, n0, acc);
        gather_row64(g_h2, s1, lane, n1, acc);
        gather_row64(g_h2, s2, lane, n2, acc);
        gather_row64(g_h2, s3, lane, n3, acc);
    }
    for (; e < end; e++) {
        unsigned long long p0 = g_edge_p[e];
        int   s0 = (int)(uint32_t)p0;
        float n0 = __uint_as_float((uint32_t)(p0 >> 32)) * dv;
        gather_row64(g_h2, s0, lane, n0, acc);
    }
    gather_row64(g_h2, node, lane, dv * dv, acc);   // self loop

    float2 r;
    r.x = acc[0] + bias[lane*2+0];
    r.y = acc[1] + bias[lane*2+1];
    *(float2*)&out[(size_t)node * 64 + lane * 2] = r;
}

// ---------------- launch ----------------
extern "C" void kernel_launch(void* const* d_in, const int* in_sizes, int n_in,
                              void* d_out, int out_size) {
    const float* x  = (const float*)d_in[0];
    const int*   ei = (const int*)  d_in[1];
    const float* w  = (const float*)d_in[2];
    const float* W1 = (const float*)d_in[3];
    const float* b1 = (const float*)d_in[4];
    const float* W2 = (const float*)d_in[5];
    const float* b2 = (const float*)d_in[6];
    float* out = (float*)d_out;

    int E = in_sizes[1] / 2;
    int n = in_sizes[0] / 128;
    const int* src = ei;
    const int* dst = ei + E;

    int nb_n = (n + 255) / 256;
    int nb_e = (E + 255) / 256;
    int nb_s = (n + SCAN_B - 1) / SCAN_B;

    __half* W1h; cudaGetSymbolAddress((void**)&W1h, g_W1h);
    __half* W2h; cudaGetSymbolAddress((void**)&W2h, g_W2h);
    __half* h1;  cudaGetSymbolAddress((void**)&h1,  g_h1);
    __half* a1;  cudaGetSymbolAddress((void**)&a1,  g_a1);
    __half* h2;  cudaGetSymbolAddress((void**)&h2,  g_h2);

    int nb_g = (n + 127) / 128;
    int nb_a = (n + 7) / 8;

    // Fork a side stream so the CSR build overlaps the GEMM1 chain in the
    // captured graph. Created fresh each call and never destroyed (destroying
    // a capture-participating stream would invalidate the capture; a few
    // leaked handles across the harness's 2-3 calls is harmless and does not
    // allocate tracked device memory).
    cudaStream_t s1;
    cudaStreamCreateWithFlags(&s1, cudaStreamNonBlocking);
    cudaEvent_t evFork, evJoin;
    cudaEventCreateWithFlags(&evFork, cudaEventDisableTiming);
    cudaEventCreateWithFlags(&evJoin, cudaEventDisableTiming);

    cudaEventRecord(evFork, 0);                // fork point on capture stream
    cudaStreamWaitEvent(s1, evFork, 0);

    // main stream: weight convert + GEMM1
    convw_kernel<<<96, 256>>>(W1, W2, W1h, W2h);              // #1
    gemm1_kernel<<<nb_g, 256>>>(x, W1h, h1, n);               // #2

    // side stream: CSR build (independent of GEMM1)
    zero_kernel<<<nb_n, 256, 0, s1>>>(n);                     // #3
    hist_kernel<<<nb_e, 256, 0, s1>>>(dst, w, E);             // #4 <- profiled
    scan_local_kernel<<<nb_s, SCAN_B, 0, s1>>>(n);            // #5
    scan_blocks_kernel<<<1, 128, 0, s1>>>(n);                 // #6
    scan_apply_kernel<<<nb_n, 256, 0, s1>>>(n);               // #7
    scatter_kernel<<<nb_e, 256, 0, s1>>>(src, dst, w, E);     // #8

    cudaEventRecord(evJoin, s1);               // join back to capture stream
    cudaStreamWaitEvent(0, evJoin, 0);

    // tail (needs both chains)
    agg1_kernel<<<nb_a, 256>>>(b1, n);                        // #9
    gemm2_kernel<<<nb_g, 256>>>(a1, W2h, h2, n);              // #10
    agg2_kernel<<<nb_a, 256>>>(b2, out, n);                   // #11
}